// round 14
// baseline (speedup 1.0000x reference)
#include <cuda_runtime.h>
#include <cuda_bf16.h>
#include <cuda_fp16.h>
#include <math.h>
#include <stdint.h>

#define D  128
#define BB 512
#define NN 512
#define BN (BB*NN)
#define APAD 136   // fallback path: padded bf16 row
#define CAP 384    // rows cached in hop smem (cnt ~ Binom(512,.5), max ~300)

#if defined(__CUDA_ARCH__) && defined(__CUDA_ARCH_FEAT_SM103_ALL)
#define USE_TC 1
#else
#define USE_TC 0
#endif

// ---- scratch (static device arrays) ----
__device__ __align__(16) __nv_bfloat16 g_W1h[D*D];   // hi of (Wk@Wa1)^T, [d][k]
__device__ __align__(16) __nv_bfloat16 g_W1l[D*D];   // lo residual
__device__ float  g_crel[BB*D];                      // rel @ Wa3 + b_att
__device__ __half g_fk16[BN*D];                      // compacted fp16 fkW rows
__device__ int    g_rows[BN];                        // p -> global row id (b*NN+n)
__device__ int    g_bcnt[BB];
__device__ int    g_boff[BB];
__device__ int    g_total;

__device__ __forceinline__ float lrelu(float x) { return x > 0.f ? x : 0.01f*x; }

// ---- block reductions for blockDim == 512 (16 warps) ----
__device__ __forceinline__ float block_sum512(float v, float* scratch) {
    int lane = threadIdx.x & 31, w = threadIdx.x >> 5;
    #pragma unroll
    for (int o = 16; o > 0; o >>= 1) v += __shfl_down_sync(0xffffffffu, v, o);
    if (lane == 0) scratch[w] = v;
    __syncthreads();
    if (threadIdx.x < 16) {
        v = scratch[threadIdx.x];
        #pragma unroll
        for (int o = 8; o > 0; o >>= 1) v += __shfl_down_sync(0xffffu, v, o, 16);
        if (threadIdx.x == 0) scratch[0] = v;
    }
    __syncthreads();
    float r = scratch[0];
    __syncthreads();
    return r;
}

__device__ __forceinline__ float block_max512(float v, float* scratch) {
    int lane = threadIdx.x & 31, w = threadIdx.x >> 5;
    #pragma unroll
    for (int o = 16; o > 0; o >>= 1) v = fmaxf(v, __shfl_down_sync(0xffffffffu, v, o));
    if (lane == 0) scratch[w] = v;
    __syncthreads();
    if (threadIdx.x < 16) {
        v = scratch[threadIdx.x];
        #pragma unroll
        for (int o = 8; o > 0; o >>= 1) v = fmaxf(v, __shfl_down_sync(0xffffu, v, o, 16));
        if (threadIdx.x == 0) scratch[0] = v;
    }
    __syncthreads();
    float r = scratch[0];
    __syncthreads();
    return r;
}

// ---- merged prep + compaction (4-way k-split) ----
__global__ void __launch_bounds__(512) prep_compact_kernel(
    const float* __restrict__ Wk, const float* __restrict__ W_att,
    const float* __restrict__ b_att, const float* __restrict__ rel,
    const int* __restrict__ mask)
{
    int blk = blockIdx.x;
    int tid = threadIdx.x;
    __shared__ float row_s[D];
    __shared__ float part[512];

    if (blk < D) {
        if (tid < D) row_s[tid] = Wk[blk*D + tid];
        __syncthreads();
        int d = tid & 127, qq = tid >> 7;
        float acc = 0.f;
        #pragma unroll 8
        for (int j = qq*32; j < qq*32 + 32; j++)
            acc += row_s[j] * W_att[j*D + d];
        part[qq*128 + d] = acc;
        __syncthreads();
        if (tid < D) {
            float a = part[tid] + part[128+tid] + part[256+tid] + part[384+tid];
            __nv_bfloat16 hi = __float2bfloat16_rn(a);
            __nv_bfloat16 lo = __float2bfloat16_rn(a - __bfloat162float(hi));
            g_W1h[tid*D + blk] = hi;
            g_W1l[tid*D + blk] = lo;
        }
    } else if (blk < D + BB) {
        int b = blk - D;
        if (tid < D) row_s[tid] = rel[b*D + tid];
        __syncthreads();
        int d = tid & 127, qq = tid >> 7;
        float acc = 0.f;
        #pragma unroll 8
        for (int j = qq*32; j < qq*32 + 32; j++)
            acc += row_s[j] * W_att[(2*D + j)*D + d];
        part[qq*128 + d] = acc;
        __syncthreads();
        if (tid < D)
            g_crel[b*D + tid] = b_att[tid]
                + part[tid] + part[128+tid] + part[256+tid] + part[384+tid];
    } else {
        int b = blk - D - BB;
        __shared__ int wcnt[16];
        __shared__ int wbase[16];
        int lane = tid & 31, w = tid >> 5;
        bool act = (mask[b*NN + tid] != 0);
        unsigned bal = __ballot_sync(0xffffffffu, act);
        if (lane == 0) wcnt[w] = __popc(bal);
        __syncthreads();
        if (tid == 0) {
            int s = 0;
            #pragma unroll
            for (int i = 0; i < 16; i++) s += wcnt[i];
            int base = atomicAdd(&g_total, s);
            g_bcnt[b] = s;
            g_boff[b] = base;
            int bb = base;
            #pragma unroll
            for (int i = 0; i < 16; i++) { wbase[i] = bb; bb += wcnt[i]; }
        }
        __syncthreads();
        if (act) {
            int pos = wbase[w] + __popc(bal & ((1u << lane) - 1u));
            g_rows[pos] = b*NN + tid;
        }
    }
}

// ======================= sm_103a-only tcgen05 helpers =======================
#if USE_TC
__device__ __forceinline__ uint32_t smem_u32(const void* p) {
    uint32_t a;
    asm("{ .reg .u64 t; cvta.to.shared.u64 t, %1; cvt.u32.u64 %0, t; }"
        : "=r"(a) : "l"(p));
    return a;
}
__device__ __forceinline__ uint32_t elect_one() {
    uint32_t pred;
    asm volatile("{ .reg .pred p; elect.sync _|p, 0xFFFFFFFF; selp.b32 %0,1,0,p; }"
                 : "=r"(pred));
    return pred;
}
#define MBAR_INIT(a, c) \
    asm volatile("mbarrier.init.shared.b64 [%0], %1;" :: "r"(a), "r"(c) : "memory")
#define MBAR_INVAL(a) \
    asm volatile("mbarrier.inval.shared.b64 [%0];" :: "r"(a) : "memory")
#define MBAR_WAIT(a, ph) do { \
    uint32_t _m = (a), _p = (ph), _d; \
    asm volatile("{ .reg .pred p; mbarrier.try_wait.parity.acquire.cta.shared::cta.b64 p, [%1], %2; selp.b32 %0,1,0,p; }" \
        : "=r"(_d) : "r"(_m), "r"(_p) : "memory"); \
    if (!_d) { \
        asm volatile("{ .reg .pred P1; WL_%=: mbarrier.try_wait.parity.acquire.cta.shared::cta.b64 P1, [%0], %1, 0x989680; @P1 bra.uni WD_%=; bra.uni WL_%=; WD_%=: }" \
            :: "r"(_m), "r"(_p) : "memory"); \
    } \
} while (0)
#define TC_ALLOC(slot, n) \
    asm volatile("tcgen05.alloc.cta_group::1.sync.aligned.shared::cta.b32 [%0], %1;" \
                 :: "r"(slot), "r"((uint32_t)(n)) : "memory")
#define TC_DEALLOC(t, n) \
    asm volatile("tcgen05.dealloc.cta_group::1.sync.aligned.b32 %0, %1;" :: "r"(t), "r"((uint32_t)(n)))
#define TC_COMMIT(mb) \
    asm volatile("tcgen05.commit.cta_group::1.mbarrier::arrive::one.shared::cluster.b64 [%0];" \
                 :: "r"(mb) : "memory")
#define TC_FENCE_AFTER()  asm volatile("tcgen05.fence::after_thread_sync;" ::: "memory")
#define TC_FENCE_BEFORE() asm volatile("tcgen05.fence::before_thread_sync;" ::: "memory")
#define TC_WAIT_LD()      asm volatile("tcgen05.wait::ld.sync.aligned;" ::: "memory")
#define FENCE_ASYNC()     asm volatile("fence.proxy.async.shared::cta;" ::: "memory")

#define TC_LD_X32(r, ta) \
    asm volatile("tcgen05.ld.sync.aligned.32x32b.x32.b32 " \
        "{%0,%1,%2,%3,%4,%5,%6,%7,%8,%9,%10,%11,%12,%13,%14,%15," \
        " %16,%17,%18,%19,%20,%21,%22,%23,%24,%25,%26,%27,%28,%29,%30,%31}, [%32];" \
        : "=r"((r)[0]),"=r"((r)[1]),"=r"((r)[2]),"=r"((r)[3]),"=r"((r)[4]),"=r"((r)[5]), \
          "=r"((r)[6]),"=r"((r)[7]),"=r"((r)[8]),"=r"((r)[9]),"=r"((r)[10]),"=r"((r)[11]), \
          "=r"((r)[12]),"=r"((r)[13]),"=r"((r)[14]),"=r"((r)[15]),"=r"((r)[16]),"=r"((r)[17]), \
          "=r"((r)[18]),"=r"((r)[19]),"=r"((r)[20]),"=r"((r)[21]),"=r"((r)[22]),"=r"((r)[23]), \
          "=r"((r)[24]),"=r"((r)[25]),"=r"((r)[26]),"=r"((r)[27]),"=r"((r)[28]),"=r"((r)[29]), \
          "=r"((r)[30]),"=r"((r)[31]) : "r"(ta))

static __device__ __forceinline__ void tc_mma_f16_ss(
    uint32_t d_tmem, uint64_t a_desc, uint64_t b_desc, uint32_t idesc, bool en)
{
    uint32_t e = en ? 1u : 0u;
    asm volatile(
        "{\n\t.reg .pred p;\n\t"
        "setp.ne.u32 p, %5, 0;\n\t"
        "tcgen05.mma.cta_group::1.kind::f16 [%0], %1, %2, %3, {%4,%4,%4,%4}, p;\n\t}"
        :: "r"(d_tmem), "l"(a_desc), "l"(b_desc), "r"(idesc), "r"(0u), "r"(e)
        : "memory");
}
#define DESC_BASE_SW128 ((2ULL<<61) | (1ULL<<46) | (64ULL<<32) | (1ULL<<16))
#define MK_DESC(addr) (DESC_BASE_SW128 | (uint64_t)(((addr) >> 4) & 0x3FFF))
#define GEMM_IDESC 0x8200490u   // f32 out, bf16 a/b, N=128, M=128
#endif  // USE_TC

#define SWZ(o) ((o) ^ (((o) >> 3) & 0x70))
#define OFF_B_H 131072
#define OFF_B_L 163840
#define GEMM_DSMEM (196608 + 1024)

// mma.sync fallback bits (base sm_103 target)
__device__ __forceinline__ void mma_bf16(float (&d)[4], const unsigned (&a)[4],
                                         const unsigned (&b)[2]) {
    asm volatile(
        "mma.sync.aligned.m16n8k16.row.col.f32.bf16.bf16.f32 "
        "{%0,%1,%2,%3}, {%4,%5,%6,%7}, {%8,%9}, {%0,%1,%2,%3};"
        : "+f"(d[0]), "+f"(d[1]), "+f"(d[2]), "+f"(d[3])
        : "r"(a[0]), "r"(a[1]), "r"(a[2]), "r"(a[3]), "r"(b[0]), "r"(b[1]));
}
#define LDSM_X4(r0,r1,r2,r3,addr) \
    asm volatile("ldmatrix.sync.aligned.m8n8.x4.shared.b16 {%0,%1,%2,%3}, [%4];" \
                 : "=r"(r0), "=r"(r1), "=r"(r2), "=r"(r3) : "r"(addr))

#if USE_TC
// tcgen05 A loader, 512 threads: 4 threads/row, 32 floats each.
__device__ __forceinline__ void gemm_load_A_tc(
    char* gp, int buf, int tile, int total, const float* __restrict__ key,
    int ridx[2][128])
{
    int tid = threadIdx.x;
    int row = tid >> 2, quarter = tid & 3;
    int gi = tile*128 + row;
    int gr = (gi < total) ? g_rows[gi] : -1;
    if (quarter == 0) ridx[buf][row] = gr;
    char* Ah = gp + buf*65536;
    char* Al = Ah + 32768;
    uint32_t rb = (uint32_t)(((row >> 3) + ((quarter >> 1) << 4))*1024 + (row & 7)*128);
    uint32_t cbase = (uint32_t)((quarter & 1) * 64);
    const float* src = key + (size_t)(gr < 0 ? 0 : gr) * D + quarter*32;
    #pragma unroll
    for (int cc = 0; cc < 8; cc++) {
        float4 v = (gr >= 0) ? *(const float4*)(src + cc*4)
                             : make_float4(0.f, 0.f, 0.f, 0.f);
        __nv_bfloat16 h0 = __float2bfloat16_rn(v.x);
        __nv_bfloat16 h1 = __float2bfloat16_rn(v.y);
        __nv_bfloat16 h2 = __float2bfloat16_rn(v.z);
        __nv_bfloat16 h3 = __float2bfloat16_rn(v.w);
        __nv_bfloat16 l0 = __float2bfloat16_rn(v.x - __bfloat162float(h0));
        __nv_bfloat16 l1 = __float2bfloat16_rn(v.y - __bfloat162float(h1));
        __nv_bfloat16 l2 = __float2bfloat16_rn(v.z - __bfloat162float(h2));
        __nv_bfloat16 l3 = __float2bfloat16_rn(v.w - __bfloat162float(h3));
        uint32_t off = SWZ(rb + cbase + (uint32_t)(cc*8));
        __nv_bfloat162 ph0(h0, h1), ph1(h2, h3), pl0(l0, l1), pl1(l2, l3);
        uint2 uh = make_uint2(*(uint32_t*)&ph0, *(uint32_t*)&ph1);
        uint2 ul = make_uint2(*(uint32_t*)&pl0, *(uint32_t*)&pl1);
        *(uint2*)(Ah + off) = uh;
        *(uint2*)(Al + off) = ul;
    }
}
#endif

// ---- persistent GEMM (512 threads): fk16 = fp16(key@W1). No value traffic. ----
__global__ void __launch_bounds__(512) gemm_kernel(const float* __restrict__ key) {
    extern __shared__ __align__(16) char dsh[];
    __shared__ int ridx[2][128];
    int tid = threadIdx.x;
    int wid = tid >> 5, lane = tid & 31;
    int total = g_total;

#if USE_TC
    __shared__ __align__(8) unsigned long long mbar_st;
    __shared__ uint32_t tmem_slot;
    int ntiles = (total + 127) >> 7;

    uint32_t dyn = smem_u32(dsh);
    uint32_t base = (dyn + 1023) & ~1023u;
    char* gp = dsh + (base - dyn);
    uint32_t mbar = smem_u32(&mbar_st);
    uint32_t slot = smem_u32(&tmem_slot);

    if (tid == 0) MBAR_INIT(mbar, 1);
    if (wid == 0) TC_ALLOC(slot, 128);
    __syncthreads();
    uint32_t tmem;
    asm volatile("ld.shared.b32 %0, [%1];" : "=r"(tmem) : "r"(slot));

    {
        const uint4* sBh = (const uint4*)g_W1h;
        const uint4* sBl = (const uint4*)g_W1l;
        for (int i = tid; i < 2048; i += 512) {
            int d = i >> 4, c = i & 15;
            uint32_t off = (uint32_t)(((d >> 3) + ((c >> 3) << 4))*1024
                                      + (d & 7)*128 + ((c & 7) << 4));
            off = SWZ(off);
            *(uint4*)(gp + OFF_B_H + off) = sBh[i];
            *(uint4*)(gp + OFF_B_L + off) = sBl[i];
        }
    }
    if ((int)blockIdx.x < ntiles)
        gemm_load_A_tc(gp, 0, blockIdx.x, total, key, ridx);

    uint64_t dBh = MK_DESC(base + OFF_B_H);
    uint64_t dBl = MK_DESC(base + OFF_B_L);

    int bufp = 0, ph = 0;
    for (int tile = blockIdx.x; tile < ntiles; tile += gridDim.x) {
        __syncthreads();
        if (wid == 0) {
            FENCE_ASYNC();
            uint32_t ab = base + bufp*65536;
            uint64_t dAh = MK_DESC(ab);
            uint64_t dAl = MK_DESC(ab + 32768);
            if (elect_one()) {
                #pragma unroll
                for (int s = 0; s < 8; s++) {
                    uint64_t ko = (uint64_t)((s & 3)*2 + (s >> 2)*1024);
                    tc_mma_f16_ss(tmem, dAh + ko, dBh + ko, GEMM_IDESC, s > 0);
                    tc_mma_f16_ss(tmem, dAh + ko, dBl + ko, GEMM_IDESC, true);
                    tc_mma_f16_ss(tmem, dAl + ko, dBh + ko, GEMM_IDESC, true);
                }
                TC_COMMIT(mbar);
            }
        }
        int nxt = tile + gridDim.x;
        if (nxt < ntiles)
            gemm_load_A_tc(gp, bufp ^ 1, nxt, total, key, ridx);

        MBAR_WAIT(mbar, ph);
        ph ^= 1;
        TC_FENCE_AFTER();
        {
            int sub = wid & 3, cb = (wid >> 2) * 32;
            uint32_t r0[32];
            TC_LD_X32(r0, tmem + cb);
            TC_WAIT_LD();
            TC_FENCE_BEFORE();
            int prow = tile*128 + sub*32 + lane;
            __half* dst = g_fk16 + (size_t)prow * D + cb;
            uint32_t pk[16];
            #pragma unroll
            for (int i = 0; i < 16; i++) {
                __half2 h = __floats2half2_rn(__uint_as_float(r0[2*i]),
                                              __uint_as_float(r0[2*i+1]));
                pk[i] = *(uint32_t*)&h;
            }
            #pragma unroll
            for (int i = 0; i < 4; i++)
                *(uint4*)((char*)dst + i*16) = make_uint4(pk[4*i], pk[4*i+1],
                                                          pk[4*i+2], pk[4*i+3]);
        }
        bufp ^= 1;
    }
    __syncthreads();
    if (tid == 0) MBAR_INVAL(mbar);
    if (wid == 0) TC_DEALLOC(tmem, 128);

#else  // ---------------- mma.sync fallback (persistent, M=64 tiles, 512 thr) ----------------
    __nv_bfloat16* Ah = (__nv_bfloat16*)dsh;
    __nv_bfloat16* Al = Ah + 64*APAD;
    __nv_bfloat16* Bh = Al + 64*APAD;
    __nv_bfloat16* Bl = Bh + D*APAD;
    int ntiles = (total + 63) >> 6;

    {
        uint4* dBh = (uint4*)Bh;
        uint4* dBl = (uint4*)Bl;
        const uint4* sBh = (const uint4*)g_W1h;
        const uint4* sBl = (const uint4*)g_W1l;
        for (int i = tid; i < D*16; i += 512) {
            int d = i >> 4, c = i & 15;
            dBh[d*17 + c] = sBh[i];
            dBl[d*17 + c] = sBl[i];
        }
    }

    int wr = wid >> 1, wc = wid & 1;
    int grp = lane >> 2, q = lane & 3;
    int a_row = lane & 15;
    int a_koff = (lane >> 4) * 8;
    int b_row = (lane & 7) + ((lane >> 4) << 3);
    int b_koff = ((lane >> 3) & 1) * 8;
    unsigned uAh = (unsigned)__cvta_generic_to_shared(Ah);
    unsigned uAl = (unsigned)__cvta_generic_to_shared(Al);
    unsigned uBh = (unsigned)__cvta_generic_to_shared(Bh);
    unsigned uBl = (unsigned)__cvta_generic_to_shared(Bl);

    for (int tile = blockIdx.x; tile < ntiles; tile += gridDim.x) {
        __syncthreads();
        if (tid < 64) ridx[0][tid] = (tile*64 + tid < total) ? g_rows[tile*64 + tid] : -1;
        __syncthreads();
        {
            int r = tid >> 3, part = tid & 7;
            int gr = ridx[0][r];
            const float* src = (gr >= 0) ? key + (size_t)gr * D + part*16 : (const float*)0;
            #pragma unroll
            for (int c = 0; c < 16; c += 4) {
                float4 v = src ? *(const float4*)(src + c)
                               : make_float4(0.f, 0.f, 0.f, 0.f);
                int col = part*16 + c;
                __nv_bfloat16 h0 = __float2bfloat16_rn(v.x);
                __nv_bfloat16 h1 = __float2bfloat16_rn(v.y);
                __nv_bfloat16 h2 = __float2bfloat16_rn(v.z);
                __nv_bfloat16 h3 = __float2bfloat16_rn(v.w);
                __nv_bfloat16 l0 = __float2bfloat16_rn(v.x - __bfloat162float(h0));
                __nv_bfloat16 l1 = __float2bfloat16_rn(v.y - __bfloat162float(h1));
                __nv_bfloat16 l2 = __float2bfloat16_rn(v.z - __bfloat162float(h2));
                __nv_bfloat16 l3 = __float2bfloat16_rn(v.w - __bfloat162float(h3));
                __nv_bfloat162* ph = (__nv_bfloat162*)(Ah + r*APAD + col);
                __nv_bfloat162* pl = (__nv_bfloat162*)(Al + r*APAD + col);
                ph[0] = __nv_bfloat162(h0, h1); ph[1] = __nv_bfloat162(h2, h3);
                pl[0] = __nv_bfloat162(l0, l1); pl[1] = __nv_bfloat162(l2, l3);
            }
        }
        __syncthreads();

        if (wid < 8) {
            float acc[8][4];
            #pragma unroll
            for (int nt = 0; nt < 8; nt++)
                #pragma unroll
                for (int i = 0; i < 4; i++) acc[nt][i] = 0.f;

            #pragma unroll
            for (int ks = 0; ks < 8; ks++) {
                int k0 = ks * 16;
                unsigned ah[4], al[4];
                {
                    unsigned off = (unsigned)(((wr*16 + a_row)*APAD + k0 + a_koff) * 2);
                    LDSM_X4(ah[0], ah[1], ah[2], ah[3], uAh + off);
                    LDSM_X4(al[0], al[1], al[2], al[3], uAl + off);
                }
                unsigned bh[8][2], bl[8][2];
                #pragma unroll
                for (int p2 = 0; p2 < 4; p2++) {
                    unsigned off = (unsigned)(((wc*64 + p2*16 + b_row)*APAD + k0 + b_koff) * 2);
                    LDSM_X4(bh[2*p2][0], bh[2*p2][1], bh[2*p2+1][0], bh[2*p2+1][1], uBh + off);
                    LDSM_X4(bl[2*p2][0], bl[2*p2][1], bl[2*p2+1][0], bl[2*p2+1][1], uBl + off);
                }
                #pragma unroll
                for (int nt = 0; nt < 8; nt++) {
                    mma_bf16(acc[nt], ah, bh[nt]);
                    mma_bf16(acc[nt], ah, bl[nt]);
                    mma_bf16(acc[nt], al, bh[nt]);
                }
            }
            int row = wr*16 + grp;
            int p1 = tile*64 + row, p2r = p1 + 8;
            #pragma unroll
            for (int nt = 0; nt < 8; nt++) {
                int col = wc*64 + nt*8 + q*2;
                __half2 ha = __floats2half2_rn(acc[nt][0], acc[nt][1]);
                __half2 hb = __floats2half2_rn(acc[nt][2], acc[nt][3]);
                *(uint32_t*)(g_fk16 + (size_t)p1 * D + col) = *(uint32_t*)&ha;
                *(uint32_t*)(g_fk16 + (size_t)p2r * D + col) = *(uint32_t*)&hb;
            }
        }
    }
#endif
}

// ---- fused 3-hop kernel: hop0 populates smem cache; hops 1-2 run from smem ----
// Dynamic smem: fk_s[CAP][128] + v_s[CAP][128] fp16 = 196608 B -> 1 block/SM.
__global__ void __launch_bounds__(512) hop3_kernel(
    const float* __restrict__ e1,
    const float* __restrict__ value,
    const float* __restrict__ W_att,
    const float* __restrict__ W_lin,
    const float* __restrict__ b_lin,
    const float* __restrict__ Wv,
    float* __restrict__ out)
{
    extern __shared__ __align__(16) char hsm[];
    __half* fk_s = (__half*)hsm;            // [CAP][D]
    __half* v_s  = fk_s + CAP*D;            // [CAP][D]
    __shared__ __align__(16) float u_s[D];
    __shared__ __align__(16) float c_s[D];
    __shared__ float ub_s[D];
    __shared__ float crel_s[D];
    __shared__ float att_s[NN];
    __shared__ unsigned short nid_s[NN];
    __shared__ float red_s[16*D];
    __shared__ float scratch[16];

    int b = blockIdx.x;
    int tid = threadIdx.x;
    int lane = tid & 31, w = tid >> 5;

    if (tid < D) u_s[tid] = e1[b*D + tid];
    if (tid >= 256 && tid < 256 + D) crel_s[tid - 256] = g_crel[b*D + tid - 256];
    int base = g_boff[b];
    int cnt  = g_bcnt[b];
    for (int i = tid; i < cnt; i += 512)
        nid_s[i] = (unsigned short)(g_rows[base + i] & (NN - 1));
    const __half* fk_g = g_fk16 + (size_t)base * D;
    const float*  v_gb = value + (size_t)b * NN * D;
    __syncthreads();

    for (int h = 0; h < 3; h++) {
        // c = u@Wa2 + crel ; ub = lrelu(u@W_lin + b_lin) ; 2-way k-split
        {
            int d = tid & 127, hf = (tid >> 7) & 1;
            if (tid < 256) {
                float c = (hf == 0) ? crel_s[d] : 0.f;
                #pragma unroll 8
                for (int k = hf*64; k < hf*64 + 64; k++)
                    c += u_s[k] * W_att[(D + k)*D + d];
                red_s[hf*128 + d] = c;
            } else {
                float v = (hf == 0) ? b_lin[d] : 0.f;
                #pragma unroll 8
                for (int k = hf*64; k < hf*64 + 64; k++)
                    v += u_s[k] * W_lin[k*D + d];
                red_s[256 + hf*128 + d] = v;
            }
        }
        __syncthreads();
        if (tid < D) c_s[tid] = red_s[tid] + red_s[128 + tid];
        else if (tid < 2*D) {
            int d = tid - D;
            ub_s[d] = lrelu(red_s[256 + d] + red_s[384 + d]);
        }
        __syncthreads();

        float att0 = block_sum512(tid < D ? lrelu(c_s[tid]) : 0.f, scratch);

        // pass 1: logits. h==0 streams fk16 from gmem and caches into smem.
        float4 cv = *(const float4*)&c_s[lane*4];
        for (int j0 = 0; j0 < cnt; j0 += 64) {
            float ss[4];
            #pragma unroll
            for (int i = 0; i < 4; i++) ss[i] = 0.f;
            #pragma unroll
            for (int i = 0; i < 4; i++) {
                int idx = j0 + i*16 + w;
                if (idx < cnt) {
                    uint2 raw;
                    if (h == 0) {
                        raw = *(const uint2*)(fk_g + (size_t)idx*D + lane*4);
                        if (idx < CAP)
                            *(uint2*)(fk_s + idx*D + lane*4) = raw;
                    } else if (idx < CAP) {
                        raw = *(const uint2*)(fk_s + idx*D + lane*4);
                    } else {
                        raw = *(const uint2*)(fk_g + (size_t)idx*D + lane*4);
                    }
                    float2 f01 = __half22float2(*(__half2*)&raw.x);
                    float2 f23 = __half22float2(*(__half2*)&raw.y);
                    ss[i] = lrelu(f01.x+cv.x) + lrelu(f01.y+cv.y)
                          + lrelu(f23.x+cv.z) + lrelu(f23.y+cv.w);
                }
            }
            #pragma unroll
            for (int o = 16; o > 0; o >>= 1)
                #pragma unroll
                for (int i = 0; i < 4; i++)
                    ss[i] += __shfl_down_sync(0xffffffffu, ss[i], o);
            if (lane == 0) {
                #pragma unroll
                for (int i = 0; i < 4; i++) {
                    int idx = j0 + i*16 + w;
                    if (idx < cnt) att_s[idx] = ss[i];
                }
            }
        }
        __syncthreads();

        // softmax (max includes masked logit att0)
        float mx = att0;
        for (int i = tid; i < cnt; i += 512) mx = fmaxf(mx, att_s[i]);
        mx = block_max512(mx, scratch);

        float Sp = 0.f;
        for (int i = tid; i < cnt; i += 512) {
            float e = expf(att_s[i] - mx);
            att_s[i] = e;
            Sp += e;
        }
        float S = block_sum512(Sp, scratch) + 1e-5f;

        // pass 2: q = sum e * v. h==0 reads fp32 value (gather by n), caches fp16.
        float o0 = 0.f, o1 = 0.f, o2 = 0.f, o3 = 0.f;
        for (int j0 = 0; j0 < cnt; j0 += 64) {
            #pragma unroll
            for (int i = 0; i < 4; i++) {
                int idx = j0 + i*16 + w;
                if (idx < cnt) {
                    float e = att_s[idx];
                    float vx, vy, vz, vw;
                    if (h == 0) {
                        float4 v = *(const float4*)(v_gb
                                    + (size_t)nid_s[idx]*D + lane*4);
                        vx = v.x; vy = v.y; vz = v.z; vw = v.w;
                        if (idx < CAP) {
                            __half2 a = __floats2half2_rn(v.x, v.y);
                            __half2 bb = __floats2half2_rn(v.z, v.w);
                            *(uint2*)(v_s + idx*D + lane*4) =
                                make_uint2(*(uint32_t*)&a, *(uint32_t*)&bb);
                        }
                    } else if (idx < CAP) {
                        uint2 raw = *(const uint2*)(v_s + idx*D + lane*4);
                        float2 f01 = __half22float2(*(__half2*)&raw.x);
                        float2 f23 = __half22float2(*(__half2*)&raw.y);
                        vx = f01.x; vy = f01.y; vz = f23.x; vw = f23.y;
                    } else {
                        float4 v = *(const float4*)(v_gb
                                    + (size_t)nid_s[idx]*D + lane*4);
                        vx = v.x; vy = v.y; vz = v.z; vw = v.w;
                    }
                    o0 += e*vx; o1 += e*vy; o2 += e*vz; o3 += e*vw;
                }
            }
        }
        red_s[w*D + lane*4 + 0] = o0;
        red_s[w*D + lane*4 + 1] = o1;
        red_s[w*D + lane*4 + 2] = o2;
        red_s[w*D + lane*4 + 3] = o3;
        __syncthreads();

        if (tid < D) {
            float o = 0.f;
            #pragma unroll
            for (int ww = 0; ww < 16; ww++) o += red_s[ww*D + tid];
            c_s[tid] = o / S;
        }
        __syncthreads();

        if (tid < 256) {
            int d = tid & 127, hf = tid >> 7;
            float ov = 0.f;
            #pragma unroll 8
            for (int k = hf*64; k < hf*64 + 64; k++) ov += c_s[k] * Wv[k*D + d];
            red_s[hf*128 + d] = ov;
        }
        __syncthreads();
        if (tid < D) u_s[tid] = ub_s[tid] + red_s[tid] + red_s[128 + tid];
        __syncthreads();

        float nrm2 = block_sum512(tid < D ? u_s[tid]*u_s[tid] : 0.f, scratch);
        float norm = sqrtf(nrm2);
        if (tid < D) {
            float x = u_s[tid];
            float un = (norm > 1e-12f) ? (x / norm) : (x * 1e12f);
            u_s[tid] = un;
            if (h == 2) out[b*D + tid] = un;
        }
        __syncthreads();
    }
}

#define HOP_DSMEM (2 * CAP * D * (int)sizeof(__half))

extern "C" void kernel_launch(void* const* d_in, const int* in_sizes, int n_in,
                              void* d_out, int out_size) {
    const float* e1    = (const float*)d_in[0];
    const float* rel   = (const float*)d_in[1];
    const float* key   = (const float*)d_in[2];
    const float* value = (const float*)d_in[3];
    const int*   mask  = (const int*)  d_in[4];
    const float* Wk    = (const float*)d_in[5];
    const float* Wv    = (const float*)d_in[6];
    const float* Wlin  = (const float*)d_in[7];
    const float* blin  = (const float*)d_in[8];
    const float* Watt  = (const float*)d_in[9];
    const float* batt  = (const float*)d_in[10];
    float* out = (float*)d_out;

    void* total_addr = nullptr;
    cudaGetSymbolAddress(&total_addr, g_total);
    cudaMemsetAsync(total_addr, 0, sizeof(int));

    prep_compact_kernel<<<D + 2*BB, 512>>>(Wk, Watt, batt, rel, mask);

    cudaFuncSetAttribute(gemm_kernel, cudaFuncAttributeMaxDynamicSharedMemorySize,
                         GEMM_DSMEM);
    gemm_kernel<<<148, 512, GEMM_DSMEM>>>(key);

    cudaFuncSetAttribute(hop3_kernel, cudaFuncAttributeMaxDynamicSharedMemorySize,
                         HOP_DSMEM);
    hop3_kernel<<<BB, 512, HOP_DSMEM>>>(e1, value, Watt, Wlin, blin, Wv, out);
}

// round 15
// speedup vs baseline: 1.3039x; 1.3039x over previous
#include <cuda_runtime.h>
#include <cuda_bf16.h>
#include <cuda_fp16.h>
#include <math.h>
#include <stdint.h>

#define D  128
#define BB 512
#define NN 512
#define BN (BB*NN)
#define APAD 136   // fallback path: padded bf16 row

#if defined(__CUDA_ARCH__) && defined(__CUDA_ARCH_FEAT_SM103_ALL)
#define USE_TC 1
#else
#define USE_TC 0
#endif

// ---- scratch (static device arrays) ----
__device__ __align__(16) __nv_bfloat16 g_W1h[D*D];   // hi of (Wk@Wa1)^T, [d][k]
__device__ __align__(16) __nv_bfloat16 g_W1l[D*D];   // lo residual
__device__ float  g_crel[BB*D];                      // rel @ Wa3 + b_att
__device__ __half g_fk16[BN*D];                      // compacted fp16 fkW rows
__device__ __half g_v16[BN*D];                       // compacted fp16 value rows
__device__ int    g_rows[BN];                        // p -> global row id (b*NN+n)
__device__ int    g_bcnt[BB];
__device__ int    g_boff[BB];
__device__ int    g_total;

__device__ __forceinline__ float lrelu(float x) { return x > 0.f ? x : 0.01f*x; }

// ---- block reductions for blockDim == 512 (16 warps) ----
__device__ __forceinline__ float block_sum512(float v, float* scratch) {
    int lane = threadIdx.x & 31, w = threadIdx.x >> 5;
    #pragma unroll
    for (int o = 16; o > 0; o >>= 1) v += __shfl_down_sync(0xffffffffu, v, o);
    if (lane == 0) scratch[w] = v;
    __syncthreads();
    if (threadIdx.x < 16) {
        v = scratch[threadIdx.x];
        #pragma unroll
        for (int o = 8; o > 0; o >>= 1) v += __shfl_down_sync(0xffffu, v, o, 16);
        if (threadIdx.x == 0) scratch[0] = v;
    }
    __syncthreads();
    float r = scratch[0];
    __syncthreads();
    return r;
}

__device__ __forceinline__ float block_max512(float v, float* scratch) {
    int lane = threadIdx.x & 31, w = threadIdx.x >> 5;
    #pragma unroll
    for (int o = 16; o > 0; o >>= 1) v = fmaxf(v, __shfl_down_sync(0xffffffffu, v, o));
    if (lane == 0) scratch[w] = v;
    __syncthreads();
    if (threadIdx.x < 16) {
        v = scratch[threadIdx.x];
        #pragma unroll
        for (int o = 8; o > 0; o >>= 1) v = fmaxf(v, __shfl_down_sync(0xffffu, v, o, 16));
        if (threadIdx.x == 0) scratch[0] = v;
    }
    __syncthreads();
    float r = scratch[0];
    __syncthreads();
    return r;
}

// ---- merged prep + compaction (4-way k-split, all 512 threads active) ----
__global__ void __launch_bounds__(512) prep_compact_kernel(
    const float* __restrict__ Wk, const float* __restrict__ W_att,
    const float* __restrict__ b_att, const float* __restrict__ rel,
    const int* __restrict__ mask)
{
    int blk = blockIdx.x;
    int tid = threadIdx.x;
    __shared__ float row_s[D];
    __shared__ float part[512];

    if (blk < D) {
        if (tid < D) row_s[tid] = Wk[blk*D + tid];
        __syncthreads();
        int d = tid & 127, qq = tid >> 7;
        float acc = 0.f;
        #pragma unroll 8
        for (int j = qq*32; j < qq*32 + 32; j++)
            acc += row_s[j] * W_att[j*D + d];
        part[qq*128 + d] = acc;
        __syncthreads();
        if (tid < D) {
            float a = part[tid] + part[128+tid] + part[256+tid] + part[384+tid];
            __nv_bfloat16 hi = __float2bfloat16_rn(a);
            __nv_bfloat16 lo = __float2bfloat16_rn(a - __bfloat162float(hi));
            g_W1h[tid*D + blk] = hi;
            g_W1l[tid*D + blk] = lo;
        }
    } else if (blk < D + BB) {
        int b = blk - D;
        if (tid < D) row_s[tid] = rel[b*D + tid];
        __syncthreads();
        int d = tid & 127, qq = tid >> 7;
        float acc = 0.f;
        #pragma unroll 8
        for (int j = qq*32; j < qq*32 + 32; j++)
            acc += row_s[j] * W_att[(2*D + j)*D + d];
        part[qq*128 + d] = acc;
        __syncthreads();
        if (tid < D)
            g_crel[b*D + tid] = b_att[tid]
                + part[tid] + part[128+tid] + part[256+tid] + part[384+tid];
    } else {
        int b = blk - D - BB;
        __shared__ int wcnt[16];
        __shared__ int wbase[16];
        int lane = tid & 31, w = tid >> 5;
        bool act = (mask[b*NN + tid] != 0);
        unsigned bal = __ballot_sync(0xffffffffu, act);
        if (lane == 0) wcnt[w] = __popc(bal);
        __syncthreads();
        if (tid == 0) {
            int s = 0;
            #pragma unroll
            for (int i = 0; i < 16; i++) s += wcnt[i];
            int base = atomicAdd(&g_total, s);
            g_bcnt[b] = s;
            g_boff[b] = base;
            int bb = base;
            #pragma unroll
            for (int i = 0; i < 16; i++) { wbase[i] = bb; bb += wcnt[i]; }
        }
        __syncthreads();
        if (act) {
            int pos = wbase[w] + __popc(bal & ((1u << lane) - 1u));
            g_rows[pos] = b*NN + tid;
        }
    }
}

// ======================= sm_103a-only tcgen05 helpers =======================
#if USE_TC
__device__ __forceinline__ uint32_t smem_u32(const void* p) {
    uint32_t a;
    asm("{ .reg .u64 t; cvta.to.shared.u64 t, %1; cvt.u32.u64 %0, t; }"
        : "=r"(a) : "l"(p));
    return a;
}
__device__ __forceinline__ uint32_t elect_one() {
    uint32_t pred;
    asm volatile("{ .reg .pred p; elect.sync _|p, 0xFFFFFFFF; selp.b32 %0,1,0,p; }"
                 : "=r"(pred));
    return pred;
}
#define MBAR_INIT(a, c) \
    asm volatile("mbarrier.init.shared.b64 [%0], %1;" :: "r"(a), "r"(c) : "memory")
#define MBAR_INVAL(a) \
    asm volatile("mbarrier.inval.shared.b64 [%0];" :: "r"(a) : "memory")
#define MBAR_WAIT(a, ph) do { \
    uint32_t _m = (a), _p = (ph), _d; \
    asm volatile("{ .reg .pred p; mbarrier.try_wait.parity.acquire.cta.shared::cta.b64 p, [%1], %2; selp.b32 %0,1,0,p; }" \
        : "=r"(_d) : "r"(_m), "r"(_p) : "memory"); \
    if (!_d) { \
        asm volatile("{ .reg .pred P1; WL_%=: mbarrier.try_wait.parity.acquire.cta.shared::cta.b64 P1, [%0], %1, 0x989680; @P1 bra.uni WD_%=; bra.uni WL_%=; WD_%=: }" \
            :: "r"(_m), "r"(_p) : "memory"); \
    } \
} while (0)
#define TC_ALLOC(slot, n) \
    asm volatile("tcgen05.alloc.cta_group::1.sync.aligned.shared::cta.b32 [%0], %1;" \
                 :: "r"(slot), "r"((uint32_t)(n)) : "memory")
#define TC_DEALLOC(t, n) \
    asm volatile("tcgen05.dealloc.cta_group::1.sync.aligned.b32 %0, %1;" :: "r"(t), "r"((uint32_t)(n)))
#define TC_COMMIT(mb) \
    asm volatile("tcgen05.commit.cta_group::1.mbarrier::arrive::one.shared::cluster.b64 [%0];" \
                 :: "r"(mb) : "memory")
#define TC_FENCE_AFTER()  asm volatile("tcgen05.fence::after_thread_sync;" ::: "memory")
#define TC_FENCE_BEFORE() asm volatile("tcgen05.fence::before_thread_sync;" ::: "memory")
#define TC_WAIT_LD()      asm volatile("tcgen05.wait::ld.sync.aligned;" ::: "memory")
#define FENCE_ASYNC()     asm volatile("fence.proxy.async.shared::cta;" ::: "memory")

#define TC_LD_X32(r, ta) \
    asm volatile("tcgen05.ld.sync.aligned.32x32b.x32.b32 " \
        "{%0,%1,%2,%3,%4,%5,%6,%7,%8,%9,%10,%11,%12,%13,%14,%15," \
        " %16,%17,%18,%19,%20,%21,%22,%23,%24,%25,%26,%27,%28,%29,%30,%31}, [%32];" \
        : "=r"((r)[0]),"=r"((r)[1]),"=r"((r)[2]),"=r"((r)[3]),"=r"((r)[4]),"=r"((r)[5]), \
          "=r"((r)[6]),"=r"((r)[7]),"=r"((r)[8]),"=r"((r)[9]),"=r"((r)[10]),"=r"((r)[11]), \
          "=r"((r)[12]),"=r"((r)[13]),"=r"((r)[14]),"=r"((r)[15]),"=r"((r)[16]),"=r"((r)[17]), \
          "=r"((r)[18]),"=r"((r)[19]),"=r"((r)[20]),"=r"((r)[21]),"=r"((r)[22]),"=r"((r)[23]), \
          "=r"((r)[24]),"=r"((r)[25]),"=r"((r)[26]),"=r"((r)[27]),"=r"((r)[28]),"=r"((r)[29]), \
          "=r"((r)[30]),"=r"((r)[31]) : "r"(ta))

static __device__ __forceinline__ void tc_mma_f16_ss(
    uint32_t d_tmem, uint64_t a_desc, uint64_t b_desc, uint32_t idesc, bool en)
{
    uint32_t e = en ? 1u : 0u;
    asm volatile(
        "{\n\t.reg .pred p;\n\t"
        "setp.ne.u32 p, %5, 0;\n\t"
        "tcgen05.mma.cta_group::1.kind::f16 [%0], %1, %2, %3, {%4,%4,%4,%4}, p;\n\t}"
        :: "r"(d_tmem), "l"(a_desc), "l"(b_desc), "r"(idesc), "r"(0u), "r"(e)
        : "memory");
}
#define DESC_BASE_SW128 ((2ULL<<61) | (1ULL<<46) | (64ULL<<32) | (1ULL<<16))
#define MK_DESC(addr) (DESC_BASE_SW128 | (uint64_t)(((addr) >> 4) & 0x3FFF))
#define GEMM_IDESC 0x8200490u   // f32 out, bf16 a/b, N=128, M=128
#endif  // USE_TC

#define SWZ(o) ((o) ^ (((o) >> 3) & 0x70))
#define OFF_B_H 131072
#define OFF_B_L 163840
#define GEMM_DSMEM (196608 + 1024)

// mma.sync fallback bits (base sm_103 target)
__device__ __forceinline__ void mma_bf16(float (&d)[4], const unsigned (&a)[4],
                                         const unsigned (&b)[2]) {
    asm volatile(
        "mma.sync.aligned.m16n8k16.row.col.f32.bf16.bf16.f32 "
        "{%0,%1,%2,%3}, {%4,%5,%6,%7}, {%8,%9}, {%0,%1,%2,%3};"
        : "+f"(d[0]), "+f"(d[1]), "+f"(d[2]), "+f"(d[3])
        : "r"(a[0]), "r"(a[1]), "r"(a[2]), "r"(a[3]), "r"(b[0]), "r"(b[1]));
}
#define LDSM_X4(r0,r1,r2,r3,addr) \
    asm volatile("ldmatrix.sync.aligned.m8n8.x4.shared.b16 {%0,%1,%2,%3}, [%4];" \
                 : "=r"(r0), "=r"(r1), "=r"(r2), "=r"(r3) : "r"(addr))

#if USE_TC
// tcgen05 A loader, 512 threads: 4 threads/row, 32 floats each.
__device__ __forceinline__ void gemm_load_A_tc(
    char* gp, int buf, int tile, int total, const float* __restrict__ key,
    int ridx[2][128])
{
    int tid = threadIdx.x;
    int row = tid >> 2, quarter = tid & 3;
    int gi = tile*128 + row;
    int gr = (gi < total) ? g_rows[gi] : -1;
    if (quarter == 0) ridx[buf][row] = gr;
    char* Ah = gp + buf*65536;
    char* Al = Ah + 32768;
    uint32_t rb = (uint32_t)(((row >> 3) + ((quarter >> 1) << 4))*1024 + (row & 7)*128);
    uint32_t cbase = (uint32_t)((quarter & 1) * 64);
    const float* src = key + (size_t)(gr < 0 ? 0 : gr) * D + quarter*32;
    #pragma unroll
    for (int cc = 0; cc < 8; cc++) {
        float4 v = (gr >= 0) ? *(const float4*)(src + cc*4)
                             : make_float4(0.f, 0.f, 0.f, 0.f);
        __nv_bfloat16 h0 = __float2bfloat16_rn(v.x);
        __nv_bfloat16 h1 = __float2bfloat16_rn(v.y);
        __nv_bfloat16 h2 = __float2bfloat16_rn(v.z);
        __nv_bfloat16 h3 = __float2bfloat16_rn(v.w);
        __nv_bfloat16 l0 = __float2bfloat16_rn(v.x - __bfloat162float(h0));
        __nv_bfloat16 l1 = __float2bfloat16_rn(v.y - __bfloat162float(h1));
        __nv_bfloat16 l2 = __float2bfloat16_rn(v.z - __bfloat162float(h2));
        __nv_bfloat16 l3 = __float2bfloat16_rn(v.w - __bfloat162float(h3));
        uint32_t off = SWZ(rb + cbase + (uint32_t)(cc*8));
        __nv_bfloat162 ph0(h0, h1), ph1(h2, h3), pl0(l0, l1), pl1(l2, l3);
        uint2 uh = make_uint2(*(uint32_t*)&ph0, *(uint32_t*)&ph1);
        uint2 ul = make_uint2(*(uint32_t*)&pl0, *(uint32_t*)&pl1);
        *(uint2*)(Ah + off) = uh;
        *(uint2*)(Al + off) = ul;
    }
}
#endif

// ---- persistent GEMM (512 threads): fk16 = fp16(key@W1) ; v16 = fp16(value) ----
__global__ void __launch_bounds__(512) gemm_kernel(const float* __restrict__ key,
                                                   const float* __restrict__ value) {
    extern __shared__ __align__(16) char dsh[];
    __shared__ int ridx[2][128];
    int tid = threadIdx.x;
    int wid = tid >> 5, lane = tid & 31;
    int total = g_total;

#if USE_TC
    __shared__ __align__(8) unsigned long long mbar_st;
    __shared__ uint32_t tmem_slot;
    int ntiles = (total + 127) >> 7;

    uint32_t dyn = smem_u32(dsh);
    uint32_t base = (dyn + 1023) & ~1023u;
    char* gp = dsh + (base - dyn);
    uint32_t mbar = smem_u32(&mbar_st);
    uint32_t slot = smem_u32(&tmem_slot);

    if (tid == 0) MBAR_INIT(mbar, 1);
    if (wid == 0) TC_ALLOC(slot, 128);
    __syncthreads();
    uint32_t tmem;
    asm volatile("ld.shared.b32 %0, [%1];" : "=r"(tmem) : "r"(slot));

    {
        const uint4* sBh = (const uint4*)g_W1h;
        const uint4* sBl = (const uint4*)g_W1l;
        for (int i = tid; i < 2048; i += 512) {
            int d = i >> 4, c = i & 15;
            uint32_t off = (uint32_t)(((d >> 3) + ((c >> 3) << 4))*1024
                                      + (d & 7)*128 + ((c & 7) << 4));
            off = SWZ(off);
            *(uint4*)(gp + OFF_B_H + off) = sBh[i];
            *(uint4*)(gp + OFF_B_L + off) = sBl[i];
        }
    }
    if ((int)blockIdx.x < ntiles)
        gemm_load_A_tc(gp, 0, blockIdx.x, total, key, ridx);

    uint64_t dBh = MK_DESC(base + OFF_B_H);
    uint64_t dBl = MK_DESC(base + OFF_B_L);

    int bufp = 0, ph = 0;
    for (int tile = blockIdx.x; tile < ntiles; tile += gridDim.x) {
        __syncthreads();
        if (wid == 0) {
            FENCE_ASYNC();
            uint32_t ab = base + bufp*65536;
            uint64_t dAh = MK_DESC(ab);
            uint64_t dAl = MK_DESC(ab + 32768);
            if (elect_one()) {
                #pragma unroll
                for (int s = 0; s < 8; s++) {
                    uint64_t ko = (uint64_t)((s & 3)*2 + (s >> 2)*1024);
                    tc_mma_f16_ss(tmem, dAh + ko, dBh + ko, GEMM_IDESC, s > 0);
                    tc_mma_f16_ss(tmem, dAh + ko, dBl + ko, GEMM_IDESC, true);
                    tc_mma_f16_ss(tmem, dAl + ko, dBh + ko, GEMM_IDESC, true);
                }
                TC_COMMIT(mbar);
            }
        }

        // overlap with MMA: fp16 value conversion (4 threads/row)
        {
            int row = tid >> 2, quarter = tid & 3;
            int p = tile*128 + row;
            int gr = ridx[bufp][row];
            if (gr >= 0) {
                const float* vs = value + (size_t)gr * D + quarter*32;
                __half* vd = g_v16 + (size_t)p * D + quarter*32;
                #pragma unroll
                for (int c = 0; c < 32; c += 4) {
                    float4 vv = *(const float4*)(vs + c);
                    __half2 a = __floats2half2_rn(vv.x, vv.y);
                    __half2 bb = __floats2half2_rn(vv.z, vv.w);
                    uint2 pk = make_uint2(*(uint32_t*)&a, *(uint32_t*)&bb);
                    *(uint2*)(vd + c) = pk;
                }
            }
        }
        int nxt = tile + gridDim.x;
        if (nxt < ntiles)
            gemm_load_A_tc(gp, bufp ^ 1, nxt, total, key, ridx);

        MBAR_WAIT(mbar, ph);
        ph ^= 1;
        TC_FENCE_AFTER();
        {
            int sub = wid & 3, cb = (wid >> 2) * 32;
            uint32_t r0[32];
            TC_LD_X32(r0, tmem + cb);
            TC_WAIT_LD();
            TC_FENCE_BEFORE();
            int prow = tile*128 + sub*32 + lane;
            __half* dst = g_fk16 + (size_t)prow * D + cb;
            uint32_t pk[16];
            #pragma unroll
            for (int i = 0; i < 16; i++) {
                __half2 h = __floats2half2_rn(__uint_as_float(r0[2*i]),
                                              __uint_as_float(r0[2*i+1]));
                pk[i] = *(uint32_t*)&h;
            }
            #pragma unroll
            for (int i = 0; i < 4; i++)
                *(uint4*)((char*)dst + i*16) = make_uint4(pk[4*i], pk[4*i+1],
                                                          pk[4*i+2], pk[4*i+3]);
        }
        bufp ^= 1;
    }
    __syncthreads();
    if (tid == 0) MBAR_INVAL(mbar);
    if (wid == 0) TC_DEALLOC(tmem, 128);

#else  // ---------------- mma.sync fallback (persistent, M=64 tiles, 512 thr) ----------------
    __nv_bfloat16* Ah = (__nv_bfloat16*)dsh;
    __nv_bfloat16* Al = Ah + 64*APAD;
    __nv_bfloat16* Bh = Al + 64*APAD;
    __nv_bfloat16* Bl = Bh + D*APAD;
    int ntiles = (total + 63) >> 6;

    {
        uint4* dBh = (uint4*)Bh;
        uint4* dBl = (uint4*)Bl;
        const uint4* sBh = (const uint4*)g_W1h;
        const uint4* sBl = (const uint4*)g_W1l;
        for (int i = tid; i < D*16; i += 512) {
            int d = i >> 4, c = i & 15;
            dBh[d*17 + c] = sBh[i];
            dBl[d*17 + c] = sBl[i];
        }
    }

    int wr = wid >> 1, wc = wid & 1;
    int grp = lane >> 2, q = lane & 3;
    int a_row = lane & 15;
    int a_koff = (lane >> 4) * 8;
    int b_row = (lane & 7) + ((lane >> 4) << 3);
    int b_koff = ((lane >> 3) & 1) * 8;
    unsigned uAh = (unsigned)__cvta_generic_to_shared(Ah);
    unsigned uAl = (unsigned)__cvta_generic_to_shared(Al);
    unsigned uBh = (unsigned)__cvta_generic_to_shared(Bh);
    unsigned uBl = (unsigned)__cvta_generic_to_shared(Bl);

    for (int tile = blockIdx.x; tile < ntiles; tile += gridDim.x) {
        __syncthreads();
        if (tid < 64) ridx[0][tid] = (tile*64 + tid < total) ? g_rows[tile*64 + tid] : -1;
        __syncthreads();
        {
            int r = tid >> 3, part = tid & 7;
            int gr = ridx[0][r];
            const float* src = (gr >= 0) ? key + (size_t)gr * D + part*16 : (const float*)0;
            #pragma unroll
            for (int c = 0; c < 16; c += 4) {
                float4 v = src ? *(const float4*)(src + c)
                               : make_float4(0.f, 0.f, 0.f, 0.f);
                int col = part*16 + c;
                __nv_bfloat16 h0 = __float2bfloat16_rn(v.x);
                __nv_bfloat16 h1 = __float2bfloat16_rn(v.y);
                __nv_bfloat16 h2 = __float2bfloat16_rn(v.z);
                __nv_bfloat16 h3 = __float2bfloat16_rn(v.w);
                __nv_bfloat16 l0 = __float2bfloat16_rn(v.x - __bfloat162float(h0));
                __nv_bfloat16 l1 = __float2bfloat16_rn(v.y - __bfloat162float(h1));
                __nv_bfloat16 l2 = __float2bfloat16_rn(v.z - __bfloat162float(h2));
                __nv_bfloat16 l3 = __float2bfloat16_rn(v.w - __bfloat162float(h3));
                __nv_bfloat162* ph = (__nv_bfloat162*)(Ah + r*APAD + col);
                __nv_bfloat162* pl = (__nv_bfloat162*)(Al + r*APAD + col);
                ph[0] = __nv_bfloat162(h0, h1); ph[1] = __nv_bfloat162(h2, h3);
                pl[0] = __nv_bfloat162(l0, l1); pl[1] = __nv_bfloat162(l2, l3);
            }
            int p = tile*64 + r;
            if (gr >= 0) {
                const float* vs = value + (size_t)gr * D + part*16;
                __half* vd = g_v16 + (size_t)p * D + part*16;
                #pragma unroll
                for (int c = 0; c < 16; c += 4) {
                    float4 vv = *(const float4*)(vs + c);
                    __half2 a = __floats2half2_rn(vv.x, vv.y);
                    __half2 bb = __floats2half2_rn(vv.z, vv.w);
                    uint2 pk = make_uint2(*(uint32_t*)&a, *(uint32_t*)&bb);
                    *(uint2*)(vd + c) = pk;
                }
            }
        }
        __syncthreads();

        if (wid < 8) {
            float acc[8][4];
            #pragma unroll
            for (int nt = 0; nt < 8; nt++)
                #pragma unroll
                for (int i = 0; i < 4; i++) acc[nt][i] = 0.f;

            #pragma unroll
            for (int ks = 0; ks < 8; ks++) {
                int k0 = ks * 16;
                unsigned ah[4], al[4];
                {
                    unsigned off = (unsigned)(((wr*16 + a_row)*APAD + k0 + a_koff) * 2);
                    LDSM_X4(ah[0], ah[1], ah[2], ah[3], uAh + off);
                    LDSM_X4(al[0], al[1], al[2], al[3], uAl + off);
                }
                unsigned bh[8][2], bl[8][2];
                #pragma unroll
                for (int p2 = 0; p2 < 4; p2++) {
                    unsigned off = (unsigned)(((wc*64 + p2*16 + b_row)*APAD + k0 + b_koff) * 2);
                    LDSM_X4(bh[2*p2][0], bh[2*p2][1], bh[2*p2+1][0], bh[2*p2+1][1], uBh + off);
                    LDSM_X4(bl[2*p2][0], bl[2*p2][1], bl[2*p2+1][0], bl[2*p2+1][1], uBl + off);
                }
                #pragma unroll
                for (int nt = 0; nt < 8; nt++) {
                    mma_bf16(acc[nt], ah, bh[nt]);
                    mma_bf16(acc[nt], ah, bl[nt]);
                    mma_bf16(acc[nt], al, bh[nt]);
                }
            }
            int row = wr*16 + grp;
            int p1 = tile*64 + row, p2r = p1 + 8;
            #pragma unroll
            for (int nt = 0; nt < 8; nt++) {
                int col = wc*64 + nt*8 + q*2;
                __half2 ha = __floats2half2_rn(acc[nt][0], acc[nt][1]);
                __half2 hb = __floats2half2_rn(acc[nt][2], acc[nt][3]);
                *(uint32_t*)(g_fk16 + (size_t)p1 * D + col) = *(uint32_t*)&ha;
                *(uint32_t*)(g_fk16 + (size_t)p2r * D + col) = *(uint32_t*)&hb;
            }
        }
    }
#endif
}

// ---- fused 3-hop kernel: dense fp16 streams, two-pass softmax (R10/R13 body) ----
__global__ void __launch_bounds__(512) hop3_kernel(
    const float* __restrict__ e1,
    const float* __restrict__ W_att,
    const float* __restrict__ W_lin,
    const float* __restrict__ b_lin,
    const float* __restrict__ Wv,
    float* __restrict__ out)
{
    __shared__ __align__(16) float u_s[D];
    __shared__ __align__(16) float c_s[D];
    __shared__ float ub_s[D];
    __shared__ float crel_s[D];
    __shared__ float att_s[NN];
    __shared__ float red_s[16*D];
    __shared__ float scratch[16];

    int b = blockIdx.x;
    int tid = threadIdx.x;
    int lane = tid & 31, w = tid >> 5;

    if (tid < D) u_s[tid] = e1[b*D + tid];
    if (tid >= 256 && tid < 256 + D) crel_s[tid - 256] = g_crel[b*D + tid - 256];
    int base = g_boff[b];
    int cnt  = g_bcnt[b];
    const __half* fk_b = g_fk16 + (size_t)base * D;
    const __half* v_b  = g_v16 + (size_t)base * D;
    __syncthreads();

    for (int h = 0; h < 3; h++) {
        {
            int d = tid & 127, hf = (tid >> 7) & 1;
            if (tid < 256) {
                float c = (hf == 0) ? crel_s[d] : 0.f;
                #pragma unroll 8
                for (int k = hf*64; k < hf*64 + 64; k++)
                    c += u_s[k] * W_att[(D + k)*D + d];
                red_s[hf*128 + d] = c;
            } else {
                float v = (hf == 0) ? b_lin[d] : 0.f;
                #pragma unroll 8
                for (int k = hf*64; k < hf*64 + 64; k++)
                    v += u_s[k] * W_lin[k*D + d];
                red_s[256 + hf*128 + d] = v;
            }
        }
        __syncthreads();
        if (tid < D) c_s[tid] = red_s[tid] + red_s[128 + tid];
        else if (tid < 2*D) {
            int d = tid - D;
            ub_s[d] = lrelu(red_s[256 + d] + red_s[384 + d]);
        }
        __syncthreads();

        float att0 = block_sum512(tid < D ? lrelu(c_s[tid]) : 0.f, scratch);

        float4 cv = *(const float4*)&c_s[lane*4];
        for (int j0 = 0; j0 < cnt; j0 += 64) {
            float ss[4];
            #pragma unroll
            for (int i = 0; i < 4; i++) ss[i] = 0.f;
            #pragma unroll
            for (int i = 0; i < 4; i++) {
                int idx = j0 + i*16 + w;
                if (idx < cnt) {
                    uint2 raw = *(const uint2*)(fk_b + (size_t)idx*D + lane*4);
                    float2 f01 = __half22float2(*(__half2*)&raw.x);
                    float2 f23 = __half22float2(*(__half2*)&raw.y);
                    ss[i] = lrelu(f01.x+cv.x) + lrelu(f01.y+cv.y)
                          + lrelu(f23.x+cv.z) + lrelu(f23.y+cv.w);
                }
            }
            #pragma unroll
            for (int o = 16; o > 0; o >>= 1)
                #pragma unroll
                for (int i = 0; i < 4; i++)
                    ss[i] += __shfl_down_sync(0xffffffffu, ss[i], o);
            if (lane == 0) {
                #pragma unroll
                for (int i = 0; i < 4; i++) {
                    int idx = j0 + i*16 + w;
                    if (idx < cnt) att_s[idx] = ss[i];
                }
            }
        }
        __syncthreads();

        float mx = att0;
        for (int i = tid; i < cnt; i += 512) mx = fmaxf(mx, att_s[i]);
        mx = block_max512(mx, scratch);

        float Sp = 0.f;
        for (int i = tid; i < cnt; i += 512) {
            float e = expf(att_s[i] - mx);
            att_s[i] = e;
            Sp += e;
        }
        float S = block_sum512(Sp, scratch) + 1e-5f;

        float o0 = 0.f, o1 = 0.f, o2 = 0.f, o3 = 0.f;
        for (int j0 = 0; j0 < cnt; j0 += 64) {
            #pragma unroll
            for (int i = 0; i < 4; i++) {
                int idx = j0 + i*16 + w;
                if (idx < cnt) {
                    float e = att_s[idx];
                    uint2 raw = *(const uint2*)(v_b + (size_t)idx*D + lane*4);
                    float2 f01 = __half22float2(*(__half2*)&raw.x);
                    float2 f23 = __half22float2(*(__half2*)&raw.y);
                    o0 += e*f01.x; o1 += e*f01.y; o2 += e*f23.x; o3 += e*f23.y;
                }
            }
        }
        red_s[w*D + lane*4 + 0] = o0;
        red_s[w*D + lane*4 + 1] = o1;
        red_s[w*D + lane*4 + 2] = o2;
        red_s[w*D + lane*4 + 3] = o3;
        __syncthreads();

        if (tid < D) {
            float o = 0.f;
            #pragma unroll
            for (int ww = 0; ww < 16; ww++) o += red_s[ww*D + tid];
            c_s[tid] = o / S;
        }
        __syncthreads();

        if (tid < 256) {
            int d = tid & 127, hf = tid >> 7;
            float ov = 0.f;
            #pragma unroll 8
            for (int k = hf*64; k < hf*64 + 64; k++) ov += c_s[k] * Wv[k*D + d];
            red_s[hf*128 + d] = ov;
        }
        __syncthreads();
        if (tid < D) u_s[tid] = ub_s[tid] + red_s[tid] + red_s[128 + tid];
        __syncthreads();

        float nrm2 = block_sum512(tid < D ? u_s[tid]*u_s[tid] : 0.f, scratch);
        float norm = sqrtf(nrm2);
        if (tid < D) {
            float x = u_s[tid];
            float un = (norm > 1e-12f) ? (x / norm) : (x * 1e12f);
            u_s[tid] = un;
            if (h == 2) out[b*D + tid] = un;
        }
        __syncthreads();
    }
}

extern "C" void kernel_launch(void* const* d_in, const int* in_sizes, int n_in,
                              void* d_out, int out_size) {
    const float* e1    = (const float*)d_in[0];
    const float* rel   = (const float*)d_in[1];
    const float* key   = (const float*)d_in[2];
    const float* value = (const float*)d_in[3];
    const int*   mask  = (const int*)  d_in[4];
    const float* Wk    = (const float*)d_in[5];
    const float* Wv    = (const float*)d_in[6];
    const float* Wlin  = (const float*)d_in[7];
    const float* blin  = (const float*)d_in[8];
    const float* Watt  = (const float*)d_in[9];
    const float* batt  = (const float*)d_in[10];
    float* out = (float*)d_out;

    void* total_addr = nullptr;
    cudaGetSymbolAddress(&total_addr, g_total);
    cudaMemsetAsync(total_addr, 0, sizeof(int));

    prep_compact_kernel<<<D + 2*BB, 512>>>(Wk, Watt, batt, rel, mask);

    cudaFuncSetAttribute(gemm_kernel, cudaFuncAttributeMaxDynamicSharedMemorySize,
                         GEMM_DSMEM);
    gemm_kernel<<<148, 512, GEMM_DSMEM>>>(key, value);

    hop3_kernel<<<BB, 512>>>(e1, Watt, Wlin, blin, Wv, out);
}

// round 16
// speedup vs baseline: 1.4549x; 1.1158x over previous
#include <cuda_runtime.h>
#include <cuda_bf16.h>
#include <cuda_fp16.h>
#include <math.h>
#include <stdint.h>

#define D  128
#define BB 512
#define NN 512
#define BN (BB*NN)
#define APAD 136   // fallback path: padded bf16 row

#if defined(__CUDA_ARCH__) && defined(__CUDA_ARCH_FEAT_SM103_ALL)
#define USE_TC 1
#else
#define USE_TC 0
#endif

// ---- scratch (static device arrays) ----
__device__ __align__(16) __nv_bfloat16 g_W1h[D*D];   // hi of (Wk@Wa1)^T, [d][k]
__device__ __align__(16) __nv_bfloat16 g_W1l[D*D];   // lo residual
__device__ float  g_crel[BB*D];                      // rel @ Wa3 + b_att
__device__ __half g_fk16[BN*D];                      // compacted fp16 fkW rows
__device__ int    g_rows[BN];                        // p -> global row id (b*NN+n)
__device__ int    g_bcnt[BB];
__device__ int    g_boff[BB];
__device__ int    g_total;

__device__ __forceinline__ float lrelu(float x) { return x > 0.f ? x : 0.01f*x; }

// ---- block reductions for blockDim == 512 (16 warps) ----
__device__ __forceinline__ float block_sum512(float v, float* scratch) {
    int lane = threadIdx.x & 31, w = threadIdx.x >> 5;
    #pragma unroll
    for (int o = 16; o > 0; o >>= 1) v += __shfl_down_sync(0xffffffffu, v, o);
    if (lane == 0) scratch[w] = v;
    __syncthreads();
    if (threadIdx.x < 16) {
        v = scratch[threadIdx.x];
        #pragma unroll
        for (int o = 8; o > 0; o >>= 1) v += __shfl_down_sync(0xffffu, v, o, 16);
        if (threadIdx.x == 0) scratch[0] = v;
    }
    __syncthreads();
    float r = scratch[0];
    __syncthreads();
    return r;
}

__device__ __forceinline__ float block_max512(float v, float* scratch) {
    int lane = threadIdx.x & 31, w = threadIdx.x >> 5;
    #pragma unroll
    for (int o = 16; o > 0; o >>= 1) v = fmaxf(v, __shfl_down_sync(0xffffffffu, v, o));
    if (lane == 0) scratch[w] = v;
    __syncthreads();
    if (threadIdx.x < 16) {
        v = scratch[threadIdx.x];
        #pragma unroll
        for (int o = 8; o > 0; o >>= 1) v = fmaxf(v, __shfl_down_sync(0xffffu, v, o, 16));
        if (threadIdx.x == 0) scratch[0] = v;
    }
    __syncthreads();
    float r = scratch[0];
    __syncthreads();
    return r;
}

// ---- merged prep + compaction (4-way k-split, all 512 threads active) ----
__global__ void __launch_bounds__(512) prep_compact_kernel(
    const float* __restrict__ Wk, const float* __restrict__ W_att,
    const float* __restrict__ b_att, const float* __restrict__ rel,
    const int* __restrict__ mask)
{
    int blk = blockIdx.x;
    int tid = threadIdx.x;
    __shared__ float row_s[D];
    __shared__ float part[512];

    if (blk < D) {
        if (tid < D) row_s[tid] = Wk[blk*D + tid];
        __syncthreads();
        int d = tid & 127, qq = tid >> 7;
        float acc = 0.f;
        #pragma unroll 8
        for (int j = qq*32; j < qq*32 + 32; j++)
            acc += row_s[j] * W_att[j*D + d];
        part[qq*128 + d] = acc;
        __syncthreads();
        if (tid < D) {
            float a = part[tid] + part[128+tid] + part[256+tid] + part[384+tid];
            __nv_bfloat16 hi = __float2bfloat16_rn(a);
            __nv_bfloat16 lo = __float2bfloat16_rn(a - __bfloat162float(hi));
            g_W1h[tid*D + blk] = hi;
            g_W1l[tid*D + blk] = lo;
        }
    } else if (blk < D + BB) {
        int b = blk - D;
        if (tid < D) row_s[tid] = rel[b*D + tid];
        __syncthreads();
        int d = tid & 127, qq = tid >> 7;
        float acc = 0.f;
        #pragma unroll 8
        for (int j = qq*32; j < qq*32 + 32; j++)
            acc += row_s[j] * W_att[(2*D + j)*D + d];
        part[qq*128 + d] = acc;
        __syncthreads();
        if (tid < D)
            g_crel[b*D + tid] = b_att[tid]
                + part[tid] + part[128+tid] + part[256+tid] + part[384+tid];
    } else {
        int b = blk - D - BB;
        __shared__ int wcnt[16];
        __shared__ int wbase[16];
        int lane = tid & 31, w = tid >> 5;
        bool act = (mask[b*NN + tid] != 0);
        unsigned bal = __ballot_sync(0xffffffffu, act);
        if (lane == 0) wcnt[w] = __popc(bal);
        __syncthreads();
        if (tid == 0) {
            int s = 0;
            #pragma unroll
            for (int i = 0; i < 16; i++) s += wcnt[i];
            int base = atomicAdd(&g_total, s);
            g_bcnt[b] = s;
            g_boff[b] = base;
            int bb = base;
            #pragma unroll
            for (int i = 0; i < 16; i++) { wbase[i] = bb; bb += wcnt[i]; }
        }
        __syncthreads();
        if (act) {
            int pos = wbase[w] + __popc(bal & ((1u << lane) - 1u));
            g_rows[pos] = b*NN + tid;
        }
    }
}

// ======================= sm_103a-only tcgen05 helpers =======================
#if USE_TC
__device__ __forceinline__ uint32_t smem_u32(const void* p) {
    uint32_t a;
    asm("{ .reg .u64 t; cvta.to.shared.u64 t, %1; cvt.u32.u64 %0, t; }"
        : "=r"(a) : "l"(p));
    return a;
}
__device__ __forceinline__ uint32_t elect_one() {
    uint32_t pred;
    asm volatile("{ .reg .pred p; elect.sync _|p, 0xFFFFFFFF; selp.b32 %0,1,0,p; }"
                 : "=r"(pred));
    return pred;
}
#define MBAR_INIT(a, c) \
    asm volatile("mbarrier.init.shared.b64 [%0], %1;" :: "r"(a), "r"(c) : "memory")
#define MBAR_INVAL(a) \
    asm volatile("mbarrier.inval.shared.b64 [%0];" :: "r"(a) : "memory")
#define MBAR_WAIT(a, ph) do { \
    uint32_t _m = (a), _p = (ph), _d; \
    asm volatile("{ .reg .pred p; mbarrier.try_wait.parity.acquire.cta.shared::cta.b64 p, [%1], %2; selp.b32 %0,1,0,p; }" \
        : "=r"(_d) : "r"(_m), "r"(_p) : "memory"); \
    if (!_d) { \
        asm volatile("{ .reg .pred P1; WL_%=: mbarrier.try_wait.parity.acquire.cta.shared::cta.b64 P1, [%0], %1, 0x989680; @P1 bra.uni WD_%=; bra.uni WL_%=; WD_%=: }" \
            :: "r"(_m), "r"(_p) : "memory"); \
    } \
} while (0)
#define TC_ALLOC(slot, n) \
    asm volatile("tcgen05.alloc.cta_group::1.sync.aligned.shared::cta.b32 [%0], %1;" \
                 :: "r"(slot), "r"((uint32_t)(n)) : "memory")
#define TC_DEALLOC(t, n) \
    asm volatile("tcgen05.dealloc.cta_group::1.sync.aligned.b32 %0, %1;" :: "r"(t), "r"((uint32_t)(n)))
#define TC_COMMIT(mb) \
    asm volatile("tcgen05.commit.cta_group::1.mbarrier::arrive::one.shared::cluster.b64 [%0];" \
                 :: "r"(mb) : "memory")
#define TC_FENCE_AFTER()  asm volatile("tcgen05.fence::after_thread_sync;" ::: "memory")
#define TC_FENCE_BEFORE() asm volatile("tcgen05.fence::before_thread_sync;" ::: "memory")
#define TC_WAIT_LD()      asm volatile("tcgen05.wait::ld.sync.aligned;" ::: "memory")
#define FENCE_ASYNC()     asm volatile("fence.proxy.async.shared::cta;" ::: "memory")

#define TC_LD_X32(r, ta) \
    asm volatile("tcgen05.ld.sync.aligned.32x32b.x32.b32 " \
        "{%0,%1,%2,%3,%4,%5,%6,%7,%8,%9,%10,%11,%12,%13,%14,%15," \
        " %16,%17,%18,%19,%20,%21,%22,%23,%24,%25,%26,%27,%28,%29,%30,%31}, [%32];" \
        : "=r"((r)[0]),"=r"((r)[1]),"=r"((r)[2]),"=r"((r)[3]),"=r"((r)[4]),"=r"((r)[5]), \
          "=r"((r)[6]),"=r"((r)[7]),"=r"((r)[8]),"=r"((r)[9]),"=r"((r)[10]),"=r"((r)[11]), \
          "=r"((r)[12]),"=r"((r)[13]),"=r"((r)[14]),"=r"((r)[15]),"=r"((r)[16]),"=r"((r)[17]), \
          "=r"((r)[18]),"=r"((r)[19]),"=r"((r)[20]),"=r"((r)[21]),"=r"((r)[22]),"=r"((r)[23]), \
          "=r"((r)[24]),"=r"((r)[25]),"=r"((r)[26]),"=r"((r)[27]),"=r"((r)[28]),"=r"((r)[29]), \
          "=r"((r)[30]),"=r"((r)[31]) : "r"(ta))

static __device__ __forceinline__ void tc_mma_f16_ss(
    uint32_t d_tmem, uint64_t a_desc, uint64_t b_desc, uint32_t idesc, bool en)
{
    uint32_t e = en ? 1u : 0u;
    asm volatile(
        "{\n\t.reg .pred p;\n\t"
        "setp.ne.u32 p, %5, 0;\n\t"
        "tcgen05.mma.cta_group::1.kind::f16 [%0], %1, %2, %3, {%4,%4,%4,%4}, p;\n\t}"
        :: "r"(d_tmem), "l"(a_desc), "l"(b_desc), "r"(idesc), "r"(0u), "r"(e)
        : "memory");
}
#define DESC_BASE_SW128 ((2ULL<<61) | (1ULL<<46) | (64ULL<<32) | (1ULL<<16))
#define MK_DESC(addr) (DESC_BASE_SW128 | (uint64_t)(((addr) >> 4) & 0x3FFF))
#define GEMM_IDESC 0x8200490u   // f32 out, bf16 a/b, N=128, M=128
#endif  // USE_TC

#define SWZ(o) ((o) ^ (((o) >> 3) & 0x70))
#define OFF_B_H 131072
#define OFF_B_L 163840
#define GEMM_DSMEM (196608 + 1024)

// mma.sync fallback bits (base sm_103 target)
__device__ __forceinline__ void mma_bf16(float (&d)[4], const unsigned (&a)[4],
                                         const unsigned (&b)[2]) {
    asm volatile(
        "mma.sync.aligned.m16n8k16.row.col.f32.bf16.bf16.f32 "
        "{%0,%1,%2,%3}, {%4,%5,%6,%7}, {%8,%9}, {%0,%1,%2,%3};"
        : "+f"(d[0]), "+f"(d[1]), "+f"(d[2]), "+f"(d[3])
        : "r"(a[0]), "r"(a[1]), "r"(a[2]), "r"(a[3]), "r"(b[0]), "r"(b[1]));
}
#define LDSM_X4(r0,r1,r2,r3,addr) \
    asm volatile("ldmatrix.sync.aligned.m8n8.x4.shared.b16 {%0,%1,%2,%3}, [%4];" \
                 : "=r"(r0), "=r"(r1), "=r"(r2), "=r"(r3) : "r"(addr))

#if USE_TC
// tcgen05 A loader, 512 threads: 4 threads/row, 32 floats each.
__device__ __forceinline__ void gemm_load_A_tc(
    char* gp, int buf, int tile, int total, const float* __restrict__ key,
    int ridx[2][128])
{
    int tid = threadIdx.x;
    int row = tid >> 2, quarter = tid & 3;
    int gi = tile*128 + row;
    int gr = (gi < total) ? g_rows[gi] : -1;
    if (quarter == 0) ridx[buf][row] = gr;
    char* Ah = gp + buf*65536;
    char* Al = Ah + 32768;
    uint32_t rb = (uint32_t)(((row >> 3) + ((quarter >> 1) << 4))*1024 + (row & 7)*128);
    uint32_t cbase = (uint32_t)((quarter & 1) * 64);
    const float* src = key + (size_t)(gr < 0 ? 0 : gr) * D + quarter*32;
    #pragma unroll
    for (int cc = 0; cc < 8; cc++) {
        float4 v = (gr >= 0) ? *(const float4*)(src + cc*4)
                             : make_float4(0.f, 0.f, 0.f, 0.f);
        __nv_bfloat16 h0 = __float2bfloat16_rn(v.x);
        __nv_bfloat16 h1 = __float2bfloat16_rn(v.y);
        __nv_bfloat16 h2 = __float2bfloat16_rn(v.z);
        __nv_bfloat16 h3 = __float2bfloat16_rn(v.w);
        __nv_bfloat16 l0 = __float2bfloat16_rn(v.x - __bfloat162float(h0));
        __nv_bfloat16 l1 = __float2bfloat16_rn(v.y - __bfloat162float(h1));
        __nv_bfloat16 l2 = __float2bfloat16_rn(v.z - __bfloat162float(h2));
        __nv_bfloat16 l3 = __float2bfloat16_rn(v.w - __bfloat162float(h3));
        uint32_t off = SWZ(rb + cbase + (uint32_t)(cc*8));
        __nv_bfloat162 ph0(h0, h1), ph1(h2, h3), pl0(l0, l1), pl1(l2, l3);
        uint2 uh = make_uint2(*(uint32_t*)&ph0, *(uint32_t*)&ph1);
        uint2 ul = make_uint2(*(uint32_t*)&pl0, *(uint32_t*)&pl1);
        *(uint2*)(Ah + off) = uh;
        *(uint2*)(Al + off) = ul;
    }
}
#endif

// ---- persistent GEMM (512 threads): fk16 = fp16(key@W1). No value traffic. ----
__global__ void __launch_bounds__(512) gemm_kernel(const float* __restrict__ key) {
    extern __shared__ __align__(16) char dsh[];
    __shared__ int ridx[2][128];
    int tid = threadIdx.x;
    int wid = tid >> 5, lane = tid & 31;
    int total = g_total;

#if USE_TC
    __shared__ __align__(8) unsigned long long mbar_st;
    __shared__ uint32_t tmem_slot;
    int ntiles = (total + 127) >> 7;

    uint32_t dyn = smem_u32(dsh);
    uint32_t base = (dyn + 1023) & ~1023u;
    char* gp = dsh + (base - dyn);
    uint32_t mbar = smem_u32(&mbar_st);
    uint32_t slot = smem_u32(&tmem_slot);

    if (tid == 0) MBAR_INIT(mbar, 1);
    if (wid == 0) TC_ALLOC(slot, 128);
    __syncthreads();
    uint32_t tmem;
    asm volatile("ld.shared.b32 %0, [%1];" : "=r"(tmem) : "r"(slot));

    {
        const uint4* sBh = (const uint4*)g_W1h;
        const uint4* sBl = (const uint4*)g_W1l;
        for (int i = tid; i < 2048; i += 512) {
            int d = i >> 4, c = i & 15;
            uint32_t off = (uint32_t)(((d >> 3) + ((c >> 3) << 4))*1024
                                      + (d & 7)*128 + ((c & 7) << 4));
            off = SWZ(off);
            *(uint4*)(gp + OFF_B_H + off) = sBh[i];
            *(uint4*)(gp + OFF_B_L + off) = sBl[i];
        }
    }
    if ((int)blockIdx.x < ntiles)
        gemm_load_A_tc(gp, 0, blockIdx.x, total, key, ridx);

    uint64_t dBh = MK_DESC(base + OFF_B_H);
    uint64_t dBl = MK_DESC(base + OFF_B_L);

    int bufp = 0, ph = 0;
    for (int tile = blockIdx.x; tile < ntiles; tile += gridDim.x) {
        __syncthreads();
        if (wid == 0) {
            FENCE_ASYNC();
            uint32_t ab = base + bufp*65536;
            uint64_t dAh = MK_DESC(ab);
            uint64_t dAl = MK_DESC(ab + 32768);
            if (elect_one()) {
                #pragma unroll
                for (int s = 0; s < 8; s++) {
                    uint64_t ko = (uint64_t)((s & 3)*2 + (s >> 2)*1024);
                    tc_mma_f16_ss(tmem, dAh + ko, dBh + ko, GEMM_IDESC, s > 0);
                    tc_mma_f16_ss(tmem, dAh + ko, dBl + ko, GEMM_IDESC, true);
                    tc_mma_f16_ss(tmem, dAl + ko, dBh + ko, GEMM_IDESC, true);
                }
                TC_COMMIT(mbar);
            }
        }
        int nxt = tile + gridDim.x;
        if (nxt < ntiles)
            gemm_load_A_tc(gp, bufp ^ 1, nxt, total, key, ridx);

        MBAR_WAIT(mbar, ph);
        ph ^= 1;
        TC_FENCE_AFTER();
        {
            int sub = wid & 3, cb = (wid >> 2) * 32;
            uint32_t r0[32];
            TC_LD_X32(r0, tmem + cb);
            TC_WAIT_LD();
            TC_FENCE_BEFORE();
            int prow = tile*128 + sub*32 + lane;
            __half* dst = g_fk16 + (size_t)prow * D + cb;
            uint32_t pk[16];
            #pragma unroll
            for (int i = 0; i < 16; i++) {
                __half2 h = __floats2half2_rn(__uint_as_float(r0[2*i]),
                                              __uint_as_float(r0[2*i+1]));
                pk[i] = *(uint32_t*)&h;
            }
            #pragma unroll
            for (int i = 0; i < 4; i++)
                *(uint4*)((char*)dst + i*16) = make_uint4(pk[4*i], pk[4*i+1],
                                                          pk[4*i+2], pk[4*i+3]);
        }
        bufp ^= 1;
    }
    __syncthreads();
    if (tid == 0) MBAR_INVAL(mbar);
    if (wid == 0) TC_DEALLOC(tmem, 128);

#else  // ---------------- mma.sync fallback (persistent, M=64 tiles, 512 thr) ----------------
    __nv_bfloat16* Ah = (__nv_bfloat16*)dsh;
    __nv_bfloat16* Al = Ah + 64*APAD;
    __nv_bfloat16* Bh = Al + 64*APAD;
    __nv_bfloat16* Bl = Bh + D*APAD;
    int ntiles = (total + 63) >> 6;

    {
        uint4* dBh = (uint4*)Bh;
        uint4* dBl = (uint4*)Bl;
        const uint4* sBh = (const uint4*)g_W1h;
        const uint4* sBl = (const uint4*)g_W1l;
        for (int i = tid; i < D*16; i += 512) {
            int d = i >> 4, c = i & 15;
            dBh[d*17 + c] = sBh[i];
            dBl[d*17 + c] = sBl[i];
        }
    }

    int wr = wid >> 1, wc = wid & 1;
    int grp = lane >> 2, q = lane & 3;
    int a_row = lane & 15;
    int a_koff = (lane >> 4) * 8;
    int b_row = (lane & 7) + ((lane >> 4) << 3);
    int b_koff = ((lane >> 3) & 1) * 8;
    unsigned uAh = (unsigned)__cvta_generic_to_shared(Ah);
    unsigned uAl = (unsigned)__cvta_generic_to_shared(Al);
    unsigned uBh = (unsigned)__cvta_generic_to_shared(Bh);
    unsigned uBl = (unsigned)__cvta_generic_to_shared(Bl);

    for (int tile = blockIdx.x; tile < ntiles; tile += gridDim.x) {
        __syncthreads();
        if (tid < 64) ridx[0][tid] = (tile*64 + tid < total) ? g_rows[tile*64 + tid] : -1;
        __syncthreads();
        {
            int r = tid >> 3, part = tid & 7;
            int gr = ridx[0][r];
            const float* src = (gr >= 0) ? key + (size_t)gr * D + part*16 : (const float*)0;
            #pragma unroll
            for (int c = 0; c < 16; c += 4) {
                float4 v = src ? *(const float4*)(src + c)
                               : make_float4(0.f, 0.f, 0.f, 0.f);
                int col = part*16 + c;
                __nv_bfloat16 h0 = __float2bfloat16_rn(v.x);
                __nv_bfloat16 h1 = __float2bfloat16_rn(v.y);
                __nv_bfloat16 h2 = __float2bfloat16_rn(v.z);
                __nv_bfloat16 h3 = __float2bfloat16_rn(v.w);
                __nv_bfloat16 l0 = __float2bfloat16_rn(v.x - __bfloat162float(h0));
                __nv_bfloat16 l1 = __float2bfloat16_rn(v.y - __bfloat162float(h1));
                __nv_bfloat16 l2 = __float2bfloat16_rn(v.z - __bfloat162float(h2));
                __nv_bfloat16 l3 = __float2bfloat16_rn(v.w - __bfloat162float(h3));
                __nv_bfloat162* ph = (__nv_bfloat162*)(Ah + r*APAD + col);
                __nv_bfloat162* pl = (__nv_bfloat162*)(Al + r*APAD + col);
                ph[0] = __nv_bfloat162(h0, h1); ph[1] = __nv_bfloat162(h2, h3);
                pl[0] = __nv_bfloat162(l0, l1); pl[1] = __nv_bfloat162(l2, l3);
            }
        }
        __syncthreads();

        if (wid < 8) {
            float acc[8][4];
            #pragma unroll
            for (int nt = 0; nt < 8; nt++)
                #pragma unroll
                for (int i = 0; i < 4; i++) acc[nt][i] = 0.f;

            #pragma unroll
            for (int ks = 0; ks < 8; ks++) {
                int k0 = ks * 16;
                unsigned ah[4], al[4];
                {
                    unsigned off = (unsigned)(((wr*16 + a_row)*APAD + k0 + a_koff) * 2);
                    LDSM_X4(ah[0], ah[1], ah[2], ah[3], uAh + off);
                    LDSM_X4(al[0], al[1], al[2], al[3], uAl + off);
                }
                unsigned bh[8][2], bl[8][2];
                #pragma unroll
                for (int p2 = 0; p2 < 4; p2++) {
                    unsigned off = (unsigned)(((wc*64 + p2*16 + b_row)*APAD + k0 + b_koff) * 2);
                    LDSM_X4(bh[2*p2][0], bh[2*p2][1], bh[2*p2+1][0], bh[2*p2+1][1], uBh + off);
                    LDSM_X4(bl[2*p2][0], bl[2*p2][1], bl[2*p2+1][0], bl[2*p2+1][1], uBl + off);
                }
                #pragma unroll
                for (int nt = 0; nt < 8; nt++) {
                    mma_bf16(acc[nt], ah, bh[nt]);
                    mma_bf16(acc[nt], ah, bl[nt]);
                    mma_bf16(acc[nt], al, bh[nt]);
                }
            }
            int row = wr*16 + grp;
            int p1 = tile*64 + row, p2r = p1 + 8;
            #pragma unroll
            for (int nt = 0; nt < 8; nt++) {
                int col = wc*64 + nt*8 + q*2;
                __half2 ha = __floats2half2_rn(acc[nt][0], acc[nt][1]);
                __half2 hb = __floats2half2_rn(acc[nt][2], acc[nt][3]);
                *(uint32_t*)(g_fk16 + (size_t)p1 * D + col) = *(uint32_t*)&ha;
                *(uint32_t*)(g_fk16 + (size_t)p2r * D + col) = *(uint32_t*)&hb;
            }
        }
    }
#endif
}

// ---- fused 3-hop kernel: fk16 dense stream + fp32 value gather (R13 structure) ----
__global__ void __launch_bounds__(512) hop3_kernel(
    const float* __restrict__ e1,
    const float* __restrict__ value,
    const float* __restrict__ W_att,
    const float* __restrict__ W_lin,
    const float* __restrict__ b_lin,
    const float* __restrict__ Wv,
    float* __restrict__ out)
{
    __shared__ __align__(16) float u_s[D];
    __shared__ __align__(16) float c_s[D];
    __shared__ float ub_s[D];
    __shared__ float crel_s[D];
    __shared__ float att_s[NN];
    __shared__ unsigned short nid_s[NN];
    __shared__ float red_s[16*D];
    __shared__ float scratch[16];

    int b = blockIdx.x;
    int tid = threadIdx.x;
    int lane = tid & 31, w = tid >> 5;

    if (tid < D) u_s[tid] = e1[b*D + tid];
    if (tid >= 256 && tid < 256 + D) crel_s[tid - 256] = g_crel[b*D + tid - 256];
    int base = g_boff[b];
    int cnt  = g_bcnt[b];
    for (int i = tid; i < cnt; i += 512)
        nid_s[i] = (unsigned short)(g_rows[base + i] & (NN - 1));
    const __half* fk_b = g_fk16 + (size_t)base * D;
    const float*  v_gb = value + (size_t)b * NN * D;
    __syncthreads();

    for (int h = 0; h < 3; h++) {
        {
            int d = tid & 127, hf = (tid >> 7) & 1;
            if (tid < 256) {
                float c = (hf == 0) ? crel_s[d] : 0.f;
                #pragma unroll 8
                for (int k = hf*64; k < hf*64 + 64; k++)
                    c += u_s[k] * W_att[(D + k)*D + d];
                red_s[hf*128 + d] = c;
            } else {
                float v = (hf == 0) ? b_lin[d] : 0.f;
                #pragma unroll 8
                for (int k = hf*64; k < hf*64 + 64; k++)
                    v += u_s[k] * W_lin[k*D + d];
                red_s[256 + hf*128 + d] = v;
            }
        }
        __syncthreads();
        if (tid < D) c_s[tid] = red_s[tid] + red_s[128 + tid];
        else if (tid < 2*D) {
            int d = tid - D;
            ub_s[d] = lrelu(red_s[256 + d] + red_s[384 + d]);
        }
        __syncthreads();

        float att0 = block_sum512(tid < D ? lrelu(c_s[tid]) : 0.f, scratch);

        // pass 1: logits over dense fp16 fkW rows (warp per row, 4-way)
        float4 cv = *(const float4*)&c_s[lane*4];
        for (int j0 = 0; j0 < cnt; j0 += 64) {
            float ss[4];
            #pragma unroll
            for (int i = 0; i < 4; i++) ss[i] = 0.f;
            #pragma unroll
            for (int i = 0; i < 4; i++) {
                int idx = j0 + i*16 + w;
                if (idx < cnt) {
                    uint2 raw = *(const uint2*)(fk_b + (size_t)idx*D + lane*4);
                    float2 f01 = __half22float2(*(__half2*)&raw.x);
                    float2 f23 = __half22float2(*(__half2*)&raw.y);
                    ss[i] = lrelu(f01.x+cv.x) + lrelu(f01.y+cv.y)
                          + lrelu(f23.x+cv.z) + lrelu(f23.y+cv.w);
                }
            }
            #pragma unroll
            for (int o = 16; o > 0; o >>= 1)
                #pragma unroll
                for (int i = 0; i < 4; i++)
                    ss[i] += __shfl_down_sync(0xffffffffu, ss[i], o);
            if (lane == 0) {
                #pragma unroll
                for (int i = 0; i < 4; i++) {
                    int idx = j0 + i*16 + w;
                    if (idx < cnt) att_s[idx] = ss[i];
                }
            }
        }
        __syncthreads();

        float mx = att0;
        for (int i = tid; i < cnt; i += 512) mx = fmaxf(mx, att_s[i]);
        mx = block_max512(mx, scratch);

        float Sp = 0.f;
        for (int i = tid; i < cnt; i += 512) {
            float e = expf(att_s[i] - mx);
            att_s[i] = e;
            Sp += e;
        }
        float S = block_sum512(Sp, scratch) + 1e-5f;

        // pass 2: q[d] = sum e * value[b, nid, d]  (fp32 gather, coalesced per row)
        float o0 = 0.f, o1 = 0.f, o2 = 0.f, o3 = 0.f;
        for (int j0 = 0; j0 < cnt; j0 += 64) {
            #pragma unroll
            for (int i = 0; i < 4; i++) {
                int idx = j0 + i*16 + w;
                if (idx < cnt) {
                    float e = att_s[idx];
                    float4 v = *(const float4*)(v_gb
                                + (size_t)nid_s[idx]*D + lane*4);
                    o0 += e*v.x; o1 += e*v.y; o2 += e*v.z; o3 += e*v.w;
                }
            }
        }
        red_s[w*D + lane*4 + 0] = o0;
        red_s[w*D + lane*4 + 1] = o1;
        red_s[w*D + lane*4 + 2] = o2;
        red_s[w*D + lane*4 + 3] = o3;
        __syncthreads();

        if (tid < D) {
            float o = 0.f;
            #pragma unroll
            for (int ww = 0; ww < 16; ww++) o += red_s[ww*D + tid];
            c_s[tid] = o / S;
        }
        __syncthreads();

        if (tid < 256) {
            int d = tid & 127, hf = tid >> 7;
            float ov = 0.f;
            #pragma unroll 8
            for (int k = hf*64; k < hf*64 + 64; k++) ov += c_s[k] * Wv[k*D + d];
            red_s[hf*128 + d] = ov;
        }
        __syncthreads();
        if (tid < D) u_s[tid] = ub_s[tid] + red_s[tid] + red_s[128 + tid];
        __syncthreads();

        float nrm2 = block_sum512(tid < D ? u_s[tid]*u_s[tid] : 0.f, scratch);
        float norm = sqrtf(nrm2);
        if (tid < D) {
            float x = u_s[tid];
            float un = (norm > 1e-12f) ? (x / norm) : (x * 1e12f);
            u_s[tid] = un;
            if (h == 2) out[b*D + tid] = un;
        }
        __syncthreads();
    }
}

extern "C" void kernel_launch(void* const* d_in, const int* in_sizes, int n_in,
                              void* d_out, int out_size) {
    const float* e1    = (const float*)d_in[0];
    const float* rel   = (const float*)d_in[1];
    const float* key   = (const float*)d_in[2];
    const float* value = (const float*)d_in[3];
    const int*   mask  = (const int*)  d_in[4];
    const float* Wk    = (const float*)d_in[5];
    const float* Wv    = (const float*)d_in[6];
    const float* Wlin  = (const float*)d_in[7];
    const float* blin  = (const float*)d_in[8];
    const float* Watt  = (const float*)d_in[9];
    const float* batt  = (const float*)d_in[10];
    float* out = (float*)d_out;

    void* total_addr = nullptr;
    cudaGetSymbolAddress(&total_addr, g_total);
    cudaMemsetAsync(total_addr, 0, sizeof(int));

    prep_compact_kernel<<<D + 2*BB, 512>>>(Wk, Watt, batt, rel, mask);

    cudaFuncSetAttribute(gemm_kernel, cudaFuncAttributeMaxDynamicSharedMemorySize,
                         GEMM_DSMEM);
    gemm_kernel<<<148, 512, GEMM_DSMEM>>>(key);

    hop3_kernel<<<BB, 512>>>(e1, value, Watt, Wlin, blin, Wv, out);
}

// round 17
// speedup vs baseline: 1.4874x; 1.0223x over previous
#include <cuda_runtime.h>
#include <cuda_bf16.h>
#include <cuda_fp16.h>
#include <math.h>
#include <stdint.h>

#define D  128
#define BB 512
#define NN 512
#define BN (BB*NN)
#define APAD 136   // fallback path: padded bf16 row

#if defined(__CUDA_ARCH__) && defined(__CUDA_ARCH_FEAT_SM103_ALL)
#define USE_TC 1
#else
#define USE_TC 0
#endif

// ---- scratch (static device arrays) ----
__device__ __align__(16) __nv_bfloat16 g_W1h[D*D];   // hi of (Wk@Wa1)^T, [d][k]
__device__ __align__(16) __nv_bfloat16 g_W1l[D*D];   // lo residual
__device__ float  g_crel[BB*D];                      // rel @ Wa3 + b_att
__device__ __half g_fk16[BN*D];                      // compacted fp16 fkW rows
__device__ int    g_rows[BN];                        // p -> global row id (b*NN+n)
__device__ int    g_bcnt[BB];
__device__ int    g_boff[BB];
__device__ int    g_total;                           // zeroed by hop3 each run

__device__ __forceinline__ float lrelu(float x) { return x > 0.f ? x : 0.01f*x; }

// ---- block reductions for blockDim == 512 (16 warps) ----
__device__ __forceinline__ float block_sum512(float v, float* scratch) {
    int lane = threadIdx.x & 31, w = threadIdx.x >> 5;
    #pragma unroll
    for (int o = 16; o > 0; o >>= 1) v += __shfl_down_sync(0xffffffffu, v, o);
    if (lane == 0) scratch[w] = v;
    __syncthreads();
    if (threadIdx.x < 16) {
        v = scratch[threadIdx.x];
        #pragma unroll
        for (int o = 8; o > 0; o >>= 1) v += __shfl_down_sync(0xffffu, v, o, 16);
        if (threadIdx.x == 0) scratch[0] = v;
    }
    __syncthreads();
    float r = scratch[0];
    __syncthreads();
    return r;
}

__device__ __forceinline__ float block_max512(float v, float* scratch) {
    int lane = threadIdx.x & 31, w = threadIdx.x >> 5;
    #pragma unroll
    for (int o = 16; o > 0; o >>= 1) v = fmaxf(v, __shfl_down_sync(0xffffffffu, v, o));
    if (lane == 0) scratch[w] = v;
    __syncthreads();
    if (threadIdx.x < 16) {
        v = scratch[threadIdx.x];
        #pragma unroll
        for (int o = 8; o > 0; o >>= 1) v = fmaxf(v, __shfl_down_sync(0xffffu, v, o, 16));
        if (threadIdx.x == 0) scratch[0] = v;
    }
    __syncthreads();
    float r = scratch[0];
    __syncthreads();
    return r;
}

// ---- merged prep + compaction (4-way k-split, all 512 threads active) ----
__global__ void __launch_bounds__(512) prep_compact_kernel(
    const float* __restrict__ Wk, const float* __restrict__ W_att,
    const float* __restrict__ b_att, const float* __restrict__ rel,
    const int* __restrict__ mask)
{
    int blk = blockIdx.x;
    int tid = threadIdx.x;
    __shared__ float row_s[D];
    __shared__ float part[512];

    if (blk < D) {
        if (tid < D) row_s[tid] = Wk[blk*D + tid];
        __syncthreads();
        int d = tid & 127, qq = tid >> 7;
        float acc = 0.f;
        #pragma unroll 8
        for (int j = qq*32; j < qq*32 + 32; j++)
            acc += row_s[j] * W_att[j*D + d];
        part[qq*128 + d] = acc;
        __syncthreads();
        if (tid < D) {
            float a = part[tid] + part[128+tid] + part[256+tid] + part[384+tid];
            __nv_bfloat16 hi = __float2bfloat16_rn(a);
            __nv_bfloat16 lo = __float2bfloat16_rn(a - __bfloat162float(hi));
            g_W1h[tid*D + blk] = hi;
            g_W1l[tid*D + blk] = lo;
        }
    } else if (blk < D + BB) {
        int b = blk - D;
        if (tid < D) row_s[tid] = rel[b*D + tid];
        __syncthreads();
        int d = tid & 127, qq = tid >> 7;
        float acc = 0.f;
        #pragma unroll 8
        for (int j = qq*32; j < qq*32 + 32; j++)
            acc += row_s[j] * W_att[(2*D + j)*D + d];
        part[qq*128 + d] = acc;
        __syncthreads();
        if (tid < D)
            g_crel[b*D + tid] = b_att[tid]
                + part[tid] + part[128+tid] + part[256+tid] + part[384+tid];
    } else {
        int b = blk - D - BB;
        __shared__ int wcnt[16];
        __shared__ int wbase[16];
        int lane = tid & 31, w = tid >> 5;
        bool act = (mask[b*NN + tid] != 0);
        unsigned bal = __ballot_sync(0xffffffffu, act);
        if (lane == 0) wcnt[w] = __popc(bal);
        __syncthreads();
        if (tid == 0) {
            int s = 0;
            #pragma unroll
            for (int i = 0; i < 16; i++) s += wcnt[i];
            int base = atomicAdd(&g_total, s);
            g_bcnt[b] = s;
            g_boff[b] = base;
            int bb = base;
            #pragma unroll
            for (int i = 0; i < 16; i++) { wbase[i] = bb; bb += wcnt[i]; }
        }
        __syncthreads();
        if (act) {
            int pos = wbase[w] + __popc(bal & ((1u << lane) - 1u));
            g_rows[pos] = b*NN + tid;
        }
    }
}

// ======================= sm_103a-only tcgen05 helpers =======================
#if USE_TC
__device__ __forceinline__ uint32_t smem_u32(const void* p) {
    uint32_t a;
    asm("{ .reg .u64 t; cvta.to.shared.u64 t, %1; cvt.u32.u64 %0, t; }"
        : "=r"(a) : "l"(p));
    return a;
}
__device__ __forceinline__ uint32_t elect_one() {
    uint32_t pred;
    asm volatile("{ .reg .pred p; elect.sync _|p, 0xFFFFFFFF; selp.b32 %0,1,0,p; }"
                 : "=r"(pred));
    return pred;
}
#define MBAR_INIT(a, c) \
    asm volatile("mbarrier.init.shared.b64 [%0], %1;" :: "r"(a), "r"(c) : "memory")
#define MBAR_INVAL(a) \
    asm volatile("mbarrier.inval.shared.b64 [%0];" :: "r"(a) : "memory")
#define MBAR_WAIT(a, ph) do { \
    uint32_t _m = (a), _p = (ph), _d; \
    asm volatile("{ .reg .pred p; mbarrier.try_wait.parity.acquire.cta.shared::cta.b64 p, [%1], %2; selp.b32 %0,1,0,p; }" \
        : "=r"(_d) : "r"(_m), "r"(_p) : "memory"); \
    if (!_d) { \
        asm volatile("{ .reg .pred P1; WL_%=: mbarrier.try_wait.parity.acquire.cta.shared::cta.b64 P1, [%0], %1, 0x989680; @P1 bra.uni WD_%=; bra.uni WL_%=; WD_%=: }" \
            :: "r"(_m), "r"(_p) : "memory"); \
    } \
} while (0)
#define TC_ALLOC(slot, n) \
    asm volatile("tcgen05.alloc.cta_group::1.sync.aligned.shared::cta.b32 [%0], %1;" \
                 :: "r"(slot), "r"((uint32_t)(n)) : "memory")
#define TC_DEALLOC(t, n) \
    asm volatile("tcgen05.dealloc.cta_group::1.sync.aligned.b32 %0, %1;" :: "r"(t), "r"((uint32_t)(n)))
#define TC_COMMIT(mb) \
    asm volatile("tcgen05.commit.cta_group::1.mbarrier::arrive::one.shared::cluster.b64 [%0];" \
                 :: "r"(mb) : "memory")
#define TC_FENCE_AFTER()  asm volatile("tcgen05.fence::after_thread_sync;" ::: "memory")
#define TC_FENCE_BEFORE() asm volatile("tcgen05.fence::before_thread_sync;" ::: "memory")
#define TC_WAIT_LD()      asm volatile("tcgen05.wait::ld.sync.aligned;" ::: "memory")
#define FENCE_ASYNC()     asm volatile("fence.proxy.async.shared::cta;" ::: "memory")

#define TC_LD_X32(r, ta) \
    asm volatile("tcgen05.ld.sync.aligned.32x32b.x32.b32 " \
        "{%0,%1,%2,%3,%4,%5,%6,%7,%8,%9,%10,%11,%12,%13,%14,%15," \
        " %16,%17,%18,%19,%20,%21,%22,%23,%24,%25,%26,%27,%28,%29,%30,%31}, [%32];" \
        : "=r"((r)[0]),"=r"((r)[1]),"=r"((r)[2]),"=r"((r)[3]),"=r"((r)[4]),"=r"((r)[5]), \
          "=r"((r)[6]),"=r"((r)[7]),"=r"((r)[8]),"=r"((r)[9]),"=r"((r)[10]),"=r"((r)[11]), \
          "=r"((r)[12]),"=r"((r)[13]),"=r"((r)[14]),"=r"((r)[15]),"=r"((r)[16]),"=r"((r)[17]), \
          "=r"((r)[18]),"=r"((r)[19]),"=r"((r)[20]),"=r"((r)[21]),"=r"((r)[22]),"=r"((r)[23]), \
          "=r"((r)[24]),"=r"((r)[25]),"=r"((r)[26]),"=r"((r)[27]),"=r"((r)[28]),"=r"((r)[29]), \
          "=r"((r)[30]),"=r"((r)[31]) : "r"(ta))

static __device__ __forceinline__ void tc_mma_f16_ss(
    uint32_t d_tmem, uint64_t a_desc, uint64_t b_desc, uint32_t idesc, bool en)
{
    uint32_t e = en ? 1u : 0u;
    asm volatile(
        "{\n\t.reg .pred p;\n\t"
        "setp.ne.u32 p, %5, 0;\n\t"
        "tcgen05.mma.cta_group::1.kind::f16 [%0], %1, %2, %3, {%4,%4,%4,%4}, p;\n\t}"
        :: "r"(d_tmem), "l"(a_desc), "l"(b_desc), "r"(idesc), "r"(0u), "r"(e)
        : "memory");
}
#define DESC_BASE_SW128 ((2ULL<<61) | (1ULL<<46) | (64ULL<<32) | (1ULL<<16))
#define MK_DESC(addr) (DESC_BASE_SW128 | (uint64_t)(((addr) >> 4) & 0x3FFF))
#define GEMM_IDESC 0x8200490u   // f32 out, bf16 a/b, N=128, M=128
#endif  // USE_TC

#define SWZ(o) ((o) ^ (((o) >> 3) & 0x70))
#define OFF_B_H 131072
#define OFF_B_L 163840
#define GEMM_DSMEM (196608 + 1024)

// mma.sync fallback bits (base sm_103 target)
__device__ __forceinline__ void mma_bf16(float (&d)[4], const unsigned (&a)[4],
                                         const unsigned (&b)[2]) {
    asm volatile(
        "mma.sync.aligned.m16n8k16.row.col.f32.bf16.bf16.f32 "
        "{%0,%1,%2,%3}, {%4,%5,%6,%7}, {%8,%9}, {%0,%1,%2,%3};"
        : "+f"(d[0]), "+f"(d[1]), "+f"(d[2]), "+f"(d[3])
        : "r"(a[0]), "r"(a[1]), "r"(a[2]), "r"(a[3]), "r"(b[0]), "r"(b[1]));
}
#define LDSM_X4(r0,r1,r2,r3,addr) \
    asm volatile("ldmatrix.sync.aligned.m8n8.x4.shared.b16 {%0,%1,%2,%3}, [%4];" \
                 : "=r"(r0), "=r"(r1), "=r"(r2), "=r"(r3) : "r"(addr))

#if USE_TC
// tcgen05 A loader, 512 threads: 4 threads/row, 32 floats each.
__device__ __forceinline__ void gemm_load_A_tc(
    char* gp, int buf, int tile, int total, const float* __restrict__ key,
    int ridx[2][128])
{
    int tid = threadIdx.x;
    int row = tid >> 2, quarter = tid & 3;
    int gi = tile*128 + row;
    int gr = (gi < total) ? g_rows[gi] : -1;
    if (quarter == 0) ridx[buf][row] = gr;
    char* Ah = gp + buf*65536;
    char* Al = Ah + 32768;
    uint32_t rb = (uint32_t)(((row >> 3) + ((quarter >> 1) << 4))*1024 + (row & 7)*128);
    uint32_t cbase = (uint32_t)((quarter & 1) * 64);
    const float* src = key + (size_t)(gr < 0 ? 0 : gr) * D + quarter*32;
    #pragma unroll
    for (int cc = 0; cc < 8; cc++) {
        float4 v = (gr >= 0) ? *(const float4*)(src + cc*4)
                             : make_float4(0.f, 0.f, 0.f, 0.f);
        __nv_bfloat16 h0 = __float2bfloat16_rn(v.x);
        __nv_bfloat16 h1 = __float2bfloat16_rn(v.y);
        __nv_bfloat16 h2 = __float2bfloat16_rn(v.z);
        __nv_bfloat16 h3 = __float2bfloat16_rn(v.w);
        __nv_bfloat16 l0 = __float2bfloat16_rn(v.x - __bfloat162float(h0));
        __nv_bfloat16 l1 = __float2bfloat16_rn(v.y - __bfloat162float(h1));
        __nv_bfloat16 l2 = __float2bfloat16_rn(v.z - __bfloat162float(h2));
        __nv_bfloat16 l3 = __float2bfloat16_rn(v.w - __bfloat162float(h3));
        uint32_t off = SWZ(rb + cbase + (uint32_t)(cc*8));
        __nv_bfloat162 ph0(h0, h1), ph1(h2, h3), pl0(l0, l1), pl1(l2, l3);
        uint2 uh = make_uint2(*(uint32_t*)&ph0, *(uint32_t*)&ph1);
        uint2 ul = make_uint2(*(uint32_t*)&pl0, *(uint32_t*)&pl1);
        *(uint2*)(Ah + off) = uh;
        *(uint2*)(Al + off) = ul;
    }
}
#endif

// ---- persistent GEMM (512 threads): fk16 = fp16(key@W1). No value traffic. ----
__global__ void __launch_bounds__(512) gemm_kernel(const float* __restrict__ key) {
    extern __shared__ __align__(16) char dsh[];
    __shared__ int ridx[2][128];
    int tid = threadIdx.x;
    int wid = tid >> 5, lane = tid & 31;
    int total = g_total;

#if USE_TC
    __shared__ __align__(8) unsigned long long mbar_st;
    __shared__ uint32_t tmem_slot;
    int ntiles = (total + 127) >> 7;

    uint32_t dyn = smem_u32(dsh);
    uint32_t base = (dyn + 1023) & ~1023u;
    char* gp = dsh + (base - dyn);
    uint32_t mbar = smem_u32(&mbar_st);
    uint32_t slot = smem_u32(&tmem_slot);

    if (tid == 0) MBAR_INIT(mbar, 1);
    if (wid == 0) TC_ALLOC(slot, 128);
    __syncthreads();
    uint32_t tmem;
    asm volatile("ld.shared.b32 %0, [%1];" : "=r"(tmem) : "r"(slot));

    {
        const uint4* sBh = (const uint4*)g_W1h;
        const uint4* sBl = (const uint4*)g_W1l;
        for (int i = tid; i < 2048; i += 512) {
            int d = i >> 4, c = i & 15;
            uint32_t off = (uint32_t)(((d >> 3) + ((c >> 3) << 4))*1024
                                      + (d & 7)*128 + ((c & 7) << 4));
            off = SWZ(off);
            *(uint4*)(gp + OFF_B_H + off) = sBh[i];
            *(uint4*)(gp + OFF_B_L + off) = sBl[i];
        }
    }
    if ((int)blockIdx.x < ntiles)
        gemm_load_A_tc(gp, 0, blockIdx.x, total, key, ridx);

    uint64_t dBh = MK_DESC(base + OFF_B_H);
    uint64_t dBl = MK_DESC(base + OFF_B_L);

    int bufp = 0, ph = 0;
    for (int tile = blockIdx.x; tile < ntiles; tile += gridDim.x) {
        __syncthreads();
        if (wid == 0) {
            FENCE_ASYNC();
            uint32_t ab = base + bufp*65536;
            uint64_t dAh = MK_DESC(ab);
            uint64_t dAl = MK_DESC(ab + 32768);
            if (elect_one()) {
                #pragma unroll
                for (int s = 0; s < 8; s++) {
                    uint64_t ko = (uint64_t)((s & 3)*2 + (s >> 2)*1024);
                    tc_mma_f16_ss(tmem, dAh + ko, dBh + ko, GEMM_IDESC, s > 0);
                    tc_mma_f16_ss(tmem, dAh + ko, dBl + ko, GEMM_IDESC, true);
                    tc_mma_f16_ss(tmem, dAl + ko, dBh + ko, GEMM_IDESC, true);
                }
                TC_COMMIT(mbar);
            }
        }
        int nxt = tile + gridDim.x;
        if (nxt < ntiles)
            gemm_load_A_tc(gp, bufp ^ 1, nxt, total, key, ridx);

        MBAR_WAIT(mbar, ph);
        ph ^= 1;
        TC_FENCE_AFTER();
        {
            int sub = wid & 3, cb = (wid >> 2) * 32;
            uint32_t r0[32];
            TC_LD_X32(r0, tmem + cb);
            TC_WAIT_LD();
            TC_FENCE_BEFORE();
            int prow = tile*128 + sub*32 + lane;
            __half* dst = g_fk16 + (size_t)prow * D + cb;
            uint32_t pk[16];
            #pragma unroll
            for (int i = 0; i < 16; i++) {
                __half2 h = __floats2half2_rn(__uint_as_float(r0[2*i]),
                                              __uint_as_float(r0[2*i+1]));
                pk[i] = *(uint32_t*)&h;
            }
            #pragma unroll
            for (int i = 0; i < 4; i++)
                *(uint4*)((char*)dst + i*16) = make_uint4(pk[4*i], pk[4*i+1],
                                                          pk[4*i+2], pk[4*i+3]);
        }
        bufp ^= 1;
    }
    __syncthreads();
    if (tid == 0) MBAR_INVAL(mbar);
    if (wid == 0) TC_DEALLOC(tmem, 128);

#else  // ---------------- mma.sync fallback (persistent, M=64 tiles, 512 thr) ----------------
    __nv_bfloat16* Ah = (__nv_bfloat16*)dsh;
    __nv_bfloat16* Al = Ah + 64*APAD;
    __nv_bfloat16* Bh = Al + 64*APAD;
    __nv_bfloat16* Bl = Bh + D*APAD;
    int ntiles = (total + 63) >> 6;

    {
        uint4* dBh = (uint4*)Bh;
        uint4* dBl = (uint4*)Bl;
        const uint4* sBh = (const uint4*)g_W1h;
        const uint4* sBl = (const uint4*)g_W1l;
        for (int i = tid; i < D*16; i += 512) {
            int d = i >> 4, c = i & 15;
            dBh[d*17 + c] = sBh[i];
            dBl[d*17 + c] = sBl[i];
        }
    }

    int wr = wid >> 1, wc = wid & 1;
    int grp = lane >> 2, q = lane & 3;
    int a_row = lane & 15;
    int a_koff = (lane >> 4) * 8;
    int b_row = (lane & 7) + ((lane >> 4) << 3);
    int b_koff = ((lane >> 3) & 1) * 8;
    unsigned uAh = (unsigned)__cvta_generic_to_shared(Ah);
    unsigned uAl = (unsigned)__cvta_generic_to_shared(Al);
    unsigned uBh = (unsigned)__cvta_generic_to_shared(Bh);
    unsigned uBl = (unsigned)__cvta_generic_to_shared(Bl);

    for (int tile = blockIdx.x; tile < ntiles; tile += gridDim.x) {
        __syncthreads();
        if (tid < 64) ridx[0][tid] = (tile*64 + tid < total) ? g_rows[tile*64 + tid] : -1;
        __syncthreads();
        {
            int r = tid >> 3, part = tid & 7;
            int gr = ridx[0][r];
            const float* src = (gr >= 0) ? key + (size_t)gr * D + part*16 : (const float*)0;
            #pragma unroll
            for (int c = 0; c < 16; c += 4) {
                float4 v = src ? *(const float4*)(src + c)
                               : make_float4(0.f, 0.f, 0.f, 0.f);
                int col = part*16 + c;
                __nv_bfloat16 h0 = __float2bfloat16_rn(v.x);
                __nv_bfloat16 h1 = __float2bfloat16_rn(v.y);
                __nv_bfloat16 h2 = __float2bfloat16_rn(v.z);
                __nv_bfloat16 h3 = __float2bfloat16_rn(v.w);
                __nv_bfloat16 l0 = __float2bfloat16_rn(v.x - __bfloat162float(h0));
                __nv_bfloat16 l1 = __float2bfloat16_rn(v.y - __bfloat162float(h1));
                __nv_bfloat16 l2 = __float2bfloat16_rn(v.z - __bfloat162float(h2));
                __nv_bfloat16 l3 = __float2bfloat16_rn(v.w - __bfloat162float(h3));
                __nv_bfloat162* ph = (__nv_bfloat162*)(Ah + r*APAD + col);
                __nv_bfloat162* pl = (__nv_bfloat162*)(Al + r*APAD + col);
                ph[0] = __nv_bfloat162(h0, h1); ph[1] = __nv_bfloat162(h2, h3);
                pl[0] = __nv_bfloat162(l0, l1); pl[1] = __nv_bfloat162(l2, l3);
            }
        }
        __syncthreads();

        if (wid < 8) {
            float acc[8][4];
            #pragma unroll
            for (int nt = 0; nt < 8; nt++)
                #pragma unroll
                for (int i = 0; i < 4; i++) acc[nt][i] = 0.f;

            #pragma unroll
            for (int ks = 0; ks < 8; ks++) {
                int k0 = ks * 16;
                unsigned ah[4], al[4];
                {
                    unsigned off = (unsigned)(((wr*16 + a_row)*APAD + k0 + a_koff) * 2);
                    LDSM_X4(ah[0], ah[1], ah[2], ah[3], uAh + off);
                    LDSM_X4(al[0], al[1], al[2], al[3], uAl + off);
                }
                unsigned bh[8][2], bl[8][2];
                #pragma unroll
                for (int p2 = 0; p2 < 4; p2++) {
                    unsigned off = (unsigned)(((wc*64 + p2*16 + b_row)*APAD + k0 + b_koff) * 2);
                    LDSM_X4(bh[2*p2][0], bh[2*p2][1], bh[2*p2+1][0], bh[2*p2+1][1], uBh + off);
                    LDSM_X4(bl[2*p2][0], bl[2*p2][1], bl[2*p2+1][0], bl[2*p2+1][1], uBl + off);
                }
                #pragma unroll
                for (int nt = 0; nt < 8; nt++) {
                    mma_bf16(acc[nt], ah, bh[nt]);
                    mma_bf16(acc[nt], ah, bl[nt]);
                    mma_bf16(acc[nt], al, bh[nt]);
                }
            }
            int row = wr*16 + grp;
            int p1 = tile*64 + row, p2r = p1 + 8;
            #pragma unroll
            for (int nt = 0; nt < 8; nt++) {
                int col = wc*64 + nt*8 + q*2;
                __half2 ha = __floats2half2_rn(acc[nt][0], acc[nt][1]);
                __half2 hb = __floats2half2_rn(acc[nt][2], acc[nt][3]);
                *(uint32_t*)(g_fk16 + (size_t)p1 * D + col) = *(uint32_t*)&ha;
                *(uint32_t*)(g_fk16 + (size_t)p2r * D + col) = *(uint32_t*)&hb;
            }
        }
    }
#endif
}

// ---- fused 3-hop kernel: fk16 dense stream + fp32 value gather ----
__global__ void __launch_bounds__(512) hop3_kernel(
    const float* __restrict__ e1,
    const float* __restrict__ value,
    const float* __restrict__ W_att,
    const float* __restrict__ W_lin,
    const float* __restrict__ b_lin,
    const float* __restrict__ Wv,
    float* __restrict__ out)
{
    __shared__ __align__(16) float u_s[D];
    __shared__ __align__(16) float c_s[D];
    __shared__ float ub_s[D];
    __shared__ float crel_s[D];
    __shared__ float att_s[NN];
    __shared__ unsigned short nid_s[NN];
    __shared__ float red_s[16*D];
    __shared__ float scratch[16];

    int b = blockIdx.x;
    int tid = threadIdx.x;
    int lane = tid & 31, w = tid >> 5;

    // reset g_total for the next pipeline execution (gemm of THIS run already
    // consumed it; prep of the next run accumulates from 0)
    if (b == 0 && tid == 0) g_total = 0;

    if (tid < D) u_s[tid] = e1[b*D + tid];
    if (tid >= 256 && tid < 256 + D) crel_s[tid - 256] = g_crel[b*D + tid - 256];
    int base = g_boff[b];
    int cnt  = g_bcnt[b];
    for (int i = tid; i < cnt; i += 512)
        nid_s[i] = (unsigned short)(g_rows[base + i] & (NN - 1));
    const __half* fk_b = g_fk16 + (size_t)base * D;
    const float*  v_gb = value + (size_t)b * NN * D;
    __syncthreads();

    for (int h = 0; h < 3; h++) {
        {
            int d = tid & 127, hf = (tid >> 7) & 1;
            if (tid < 256) {
                float c = (hf == 0) ? crel_s[d] : 0.f;
                #pragma unroll 8
                for (int k = hf*64; k < hf*64 + 64; k++)
                    c += u_s[k] * W_att[(D + k)*D + d];
                red_s[hf*128 + d] = c;
            } else {
                float v = (hf == 0) ? b_lin[d] : 0.f;
                #pragma unroll 8
                for (int k = hf*64; k < hf*64 + 64; k++)
                    v += u_s[k] * W_lin[k*D + d];
                red_s[256 + hf*128 + d] = v;
            }
        }
        __syncthreads();
        if (tid < D) c_s[tid] = red_s[tid] + red_s[128 + tid];
        else if (tid < 2*D) {
            int d = tid - D;
            ub_s[d] = lrelu(red_s[256 + d] + red_s[384 + d]);
        }
        __syncthreads();

        float att0 = block_sum512(tid < D ? lrelu(c_s[tid]) : 0.f, scratch);

        // pass 1: logits over dense fp16 fkW rows (warp per row, 4-way)
        float4 cv = *(const float4*)&c_s[lane*4];
        for (int j0 = 0; j0 < cnt; j0 += 64) {
            float ss[4];
            #pragma unroll
            for (int i = 0; i < 4; i++) ss[i] = 0.f;
            #pragma unroll
            for (int i = 0; i < 4; i++) {
                int idx = j0 + i*16 + w;
                if (idx < cnt) {
                    uint2 raw = *(const uint2*)(fk_b + (size_t)idx*D + lane*4);
                    float2 f01 = __half22float2(*(__half2*)&raw.x);
                    float2 f23 = __half22float2(*(__half2*)&raw.y);
                    ss[i] = lrelu(f01.x+cv.x) + lrelu(f01.y+cv.y)
                          + lrelu(f23.x+cv.z) + lrelu(f23.y+cv.w);
                }
            }
            #pragma unroll
            for (int o = 16; o > 0; o >>= 1)
                #pragma unroll
                for (int i = 0; i < 4; i++)
                    ss[i] += __shfl_down_sync(0xffffffffu, ss[i], o);
            if (lane == 0) {
                #pragma unroll
                for (int i = 0; i < 4; i++) {
                    int idx = j0 + i*16 + w;
                    if (idx < cnt) att_s[idx] = ss[i];
                }
            }
        }
        __syncthreads();

        float mx = att0;
        for (int i = tid; i < cnt; i += 512) mx = fmaxf(mx, att_s[i]);
        mx = block_max512(mx, scratch);

        float Sp = 0.f;
        for (int i = tid; i < cnt; i += 512) {
            float e = expf(att_s[i] - mx);
            att_s[i] = e;
            Sp += e;
        }
        float S = block_sum512(Sp, scratch) + 1e-5f;

        // pass 2: q[d] = sum e * value[b, nid, d]  (fp32 gather)
        float o0 = 0.f, o1 = 0.f, o2 = 0.f, o3 = 0.f;
        for (int j0 = 0; j0 < cnt; j0 += 64) {
            #pragma unroll
            for (int i = 0; i < 4; i++) {
                int idx = j0 + i*16 + w;
                if (idx < cnt) {
                    float e = att_s[idx];
                    float4 v = *(const float4*)(v_gb
                                + (size_t)nid_s[idx]*D + lane*4);
                    o0 += e*v.x; o1 += e*v.y; o2 += e*v.z; o3 += e*v.w;
                }
            }
        }
        red_s[w*D + lane*4 + 0] = o0;
        red_s[w*D + lane*4 + 1] = o1;
        red_s[w*D + lane*4 + 2] = o2;
        red_s[w*D + lane*4 + 3] = o3;
        __syncthreads();

        if (tid < D) {
            float o = 0.f;
            #pragma unroll
            for (int ww = 0; ww < 16; ww++) o += red_s[ww*D + tid];
            c_s[tid] = o / S;
        }
        __syncthreads();

        if (tid < 256) {
            int d = tid & 127, hf = tid >> 7;
            float ov = 0.f;
            #pragma unroll 8
            for (int k = hf*64; k < hf*64 + 64; k++) ov += c_s[k] * Wv[k*D + d];
            red_s[hf*128 + d] = ov;
        }
        __syncthreads();
        if (tid < D) u_s[tid] = ub_s[tid] + red_s[tid] + red_s[128 + tid];
        __syncthreads();

        float nrm2 = block_sum512(tid < D ? u_s[tid]*u_s[tid] : 0.f, scratch);
        float norm = sqrtf(nrm2);
        if (tid < D) {
            float x = u_s[tid];
            float un = (norm > 1e-12f) ? (x / norm) : (x * 1e12f);
            u_s[tid] = un;
            if (h == 2) out[b*D + tid] = un;
        }
        __syncthreads();
    }
}

extern "C" void kernel_launch(void* const* d_in, const int* in_sizes, int n_in,
                              void* d_out, int out_size) {
    const float* e1    = (const float*)d_in[0];
    const float* rel   = (const float*)d_in[1];
    const float* key   = (const float*)d_in[2];
    const float* value = (const float*)d_in[3];
    const int*   mask  = (const int*)  d_in[4];
    const float* Wk    = (const float*)d_in[5];
    const float* Wv    = (const float*)d_in[6];
    const float* Wlin  = (const float*)d_in[7];
    const float* blin  = (const float*)d_in[8];
    const float* Watt  = (const float*)d_in[9];
    const float* batt  = (const float*)d_in[10];
    float* out = (float*)d_out;

    // g_total invariant: statically 0 at first call; hop3_kernel re-zeros it
    // at the end of every pipeline execution, so no memset node is needed.
    prep_compact_kernel<<<D + 2*BB, 512>>>(Wk, Watt, batt, rel, mask);

    cudaFuncSetAttribute(gemm_kernel, cudaFuncAttributeMaxDynamicSharedMemorySize,
                         GEMM_DSMEM);
    gemm_kernel<<<148, 512, GEMM_DSMEM>>>(key);

    hop3_kernel<<<BB, 512>>>(e1, value, Watt, Wlin, blin, Wv, out);
}